// round 1
// baseline (speedup 1.0000x reference)
#include <cuda_runtime.h>
#include <cuda_bf16.h>
#include <cstdint>

// Problem constants
#define BB 32
#define SS 2048
#define DD 1024
#define UU 1024
#define BS (BB*SS)            // 65536 tokens

// Output layout: context [B,D] | attn [B,S] | coverage [B,S]
#define CTX_OFF 0
#define ATTN_OFF (BB*DD)             // 32768
#define COV_OFF  (BB*DD + BB*SS)     // 98304

// Device scratch (allocation-free rule: __device__ globals)
__device__ float g_hbias[BB*UU];     // dec@Wh + Wh_b + Ws_b + Wc_b
__device__ float g_score[BS];        // pre-softmax scores

// ---------------------------------------------------------------------------
// helpers
// ---------------------------------------------------------------------------
__device__ __forceinline__ uint32_t f2tf32(float f) {
    uint32_t r;
    asm("cvt.rna.tf32.f32 %0, %1;" : "=r"(r) : "f"(f));
    return r;
}

__device__ __forceinline__ void mma_tf32(float* d, const uint32_t* a, const uint32_t* b) {
    asm volatile(
        "mma.sync.aligned.m16n8k8.row.col.f32.tf32.tf32.f32 "
        "{%0,%1,%2,%3}, {%4,%5,%6,%7}, {%8,%9}, {%0,%1,%2,%3};\n"
        : "+f"(d[0]), "+f"(d[1]), "+f"(d[2]), "+f"(d[3])
        : "r"(a[0]), "r"(a[1]), "r"(a[2]), "r"(a[3]),
          "r"(b[0]), "r"(b[1]));
}

// ---------------------------------------------------------------------------
// Kernel A: hbias[b][u] = dec[b,:]@Wh_w[:,u] + Wh_b[u] + Ws_b[u] + Wc_b[u]
// Also zeroes g_score. grid (4, 32), 256 threads.
// ---------------------------------------------------------------------------
__global__ void hbias_kernel(const float* __restrict__ dec,
                             const float* __restrict__ Whw,
                             const float* __restrict__ Whb,
                             const float* __restrict__ Wsb,
                             const float* __restrict__ Wcb) {
    __shared__ float dh[DD];
    const int b = blockIdx.y;
    const int u = blockIdx.x * 256 + threadIdx.x;
    for (int i = threadIdx.x; i < DD; i += 256) dh[i] = dec[b*DD + i];
    __syncthreads();

    float a0 = 0.f, a1 = 0.f, a2 = 0.f, a3 = 0.f;
    #pragma unroll 4
    for (int d = 0; d < DD; d += 4) {
        a0 += dh[d+0] * Whw[(size_t)(d+0)*UU + u];
        a1 += dh[d+1] * Whw[(size_t)(d+1)*UU + u];
        a2 += dh[d+2] * Whw[(size_t)(d+2)*UU + u];
        a3 += dh[d+3] * Whw[(size_t)(d+3)*UU + u];
    }
    g_hbias[b*UU + u] = (a0 + a1) + (a2 + a3) + Whb[u] + Wsb[u] + Wcb[u];

    // zero score scratch (32768 threads total; 2 each)
    int gid = (blockIdx.y * 4 + blockIdx.x) * 256 + threadIdx.x;
    g_score[gid] = 0.f;
    g_score[gid + 32768] = 0.f;
}

// ---------------------------------------------------------------------------
// Kernel B: fused  score += sum_u v[u]*tanh( X@Ws + hbias + cov*wc )  per token
// BM=128 tokens, BN=128 u-cols, BK=32. 256 threads = 8 warps (2 m x 4 n).
// grid (U/128=8, BS/128=512).
// ---------------------------------------------------------------------------
__global__ void __launch_bounds__(256, 2)
score_gemm_kernel(const float* __restrict__ X,      // enc_output [BS, D]
                  const float* __restrict__ Wsw,    // [D, U]
                  const float* __restrict__ Wcw,    // [U]
                  const float* __restrict__ Vw,     // [U]
                  const float* __restrict__ cov)    // [BS]
{
    __shared__ uint32_t As[128][36];   // [m][k], tf32 bits, pad to 36 (conflict-free)
    __shared__ uint32_t Bs[32][132];   // [k][n], pad 132
    __shared__ float hb_s[128], wc_s[128], v_s[128], cov_s[128];
    __shared__ float s_score[128];

    const int tid  = threadIdx.x;
    const int lane = tid & 31;
    const int wid  = tid >> 5;
    const int wm   = wid >> 2;        // 0..1
    const int wn   = wid & 3;         // 0..3
    const int r    = lane >> 2;       // 0..7
    const int c    = lane & 3;        // 0..3

    const int n0 = blockIdx.x * 128;
    const int m0 = blockIdx.y * 128;
    const int b  = m0 >> 11;          // m0 / 2048

    if (tid < 128) {
        hb_s[tid]  = g_hbias[b*UU + n0 + tid];
        wc_s[tid]  = Wcw[n0 + tid];
        v_s[tid]   = Vw[n0 + tid];
        cov_s[tid] = cov[m0 + tid];
        s_score[tid] = 0.f;
    }

    float acc[4][4][4] = {};

    for (int kb = 0; kb < DD; kb += 32) {
        __syncthreads();
        // load A tile: 128 rows x 32 k  (1024 float4, 4 per thread)
        #pragma unroll
        for (int l = 0; l < 4; l++) {
            int lin = tid + l * 256;
            int row = lin >> 3;
            int c4  = lin & 7;
            const float4 x = *(const float4*)&X[(size_t)(m0 + row) * DD + kb + c4 * 4];
            uint4 u;
            u.x = f2tf32(x.x); u.y = f2tf32(x.y); u.z = f2tf32(x.z); u.w = f2tf32(x.w);
            *(uint4*)&As[row][c4 * 4] = u;
        }
        // load B tile: 32 k x 128 n
        #pragma unroll
        for (int l = 0; l < 4; l++) {
            int lin = tid + l * 256;
            int br  = lin >> 5;
            int bc4 = lin & 31;
            const float4 w = *(const float4*)&Wsw[(size_t)(kb + br) * UU + n0 + bc4 * 4];
            uint4 u;
            u.x = f2tf32(w.x); u.y = f2tf32(w.y); u.z = f2tf32(w.z); u.w = f2tf32(w.w);
            *(uint4*)&Bs[br][bc4 * 4] = u;
        }
        __syncthreads();

        #pragma unroll
        for (int kk = 0; kk < 4; kk++) {
            const int k0 = kk * 8;
            uint32_t af[4][4];
            #pragma unroll
            for (int mi = 0; mi < 4; mi++) {
                const int mrow = wm * 64 + mi * 16;
                af[mi][0] = As[mrow + r    ][k0 + c    ];
                af[mi][1] = As[mrow + r + 8][k0 + c    ];
                af[mi][2] = As[mrow + r    ][k0 + c + 4];
                af[mi][3] = As[mrow + r + 8][k0 + c + 4];
            }
            uint32_t bf[4][2];
            #pragma unroll
            for (int nj = 0; nj < 4; nj++) {
                const int ncol = wn * 32 + nj * 8;
                bf[nj][0] = Bs[k0 + c    ][ncol + r];
                bf[nj][1] = Bs[k0 + c + 4][ncol + r];
            }
            #pragma unroll
            for (int mi = 0; mi < 4; mi++)
                #pragma unroll
                for (int nj = 0; nj < 4; nj++)
                    mma_tf32(acc[mi][nj], af[mi], bf[nj]);
        }
    }
    __syncthreads();

    // Epilogue: tanh + dot with V, reduce per token row
    float sp[4][2] = {};
    #pragma unroll
    for (int mi = 0; mi < 4; mi++) {
        #pragma unroll
        for (int nj = 0; nj < 4; nj++) {
            #pragma unroll
            for (int e = 0; e < 4; e++) {
                const int mloc = wm * 64 + mi * 16 + r + (e >> 1) * 8;
                const int uloc = wn * 32 + nj * 8 + 2 * c + (e & 1);
                float f = acc[mi][nj][e] + hb_s[uloc] + cov_s[mloc] * wc_s[uloc];
                sp[mi][e >> 1] += v_s[uloc] * tanhf(f);
            }
        }
    }
    #pragma unroll
    for (int mi = 0; mi < 4; mi++) {
        #pragma unroll
        for (int h = 0; h < 2; h++) {
            float v = sp[mi][h];
            v += __shfl_xor_sync(0xffffffffu, v, 1);
            v += __shfl_xor_sync(0xffffffffu, v, 2);
            if (c == 0)
                atomicAdd(&s_score[wm * 64 + mi * 16 + h * 8 + r], v);
        }
    }
    __syncthreads();
    if (tid < 128)
        atomicAdd(&g_score[m0 + tid], s_score[tid]);
}

// ---------------------------------------------------------------------------
// Kernel C1: softmax over S per batch; write attn + coverage; zero ctx region.
// grid 32, 256 threads.
// ---------------------------------------------------------------------------
__global__ void softmax_cov_kernel(const float* __restrict__ prev_cov,
                                   float* __restrict__ out) {
    __shared__ float red[256];
    const int b = blockIdx.x, tid = threadIdx.x;
    const int base = b * SS;

    float l[8];
    float mx = -1e30f;
    #pragma unroll
    for (int i = 0; i < 8; i++) {
        l[i] = g_score[base + i * 256 + tid];
        mx = fmaxf(mx, l[i]);
    }
    red[tid] = mx; __syncthreads();
    for (int o = 128; o > 0; o >>= 1) {
        if (tid < o) red[tid] = fmaxf(red[tid], red[tid + o]);
        __syncthreads();
    }
    const float gmax = red[0];
    __syncthreads();

    float s = 0.f;
    #pragma unroll
    for (int i = 0; i < 8; i++) { l[i] = expf(l[i] - gmax); s += l[i]; }
    red[tid] = s; __syncthreads();
    for (int o = 128; o > 0; o >>= 1) {
        if (tid < o) red[tid] += red[tid + o];
        __syncthreads();
    }
    const float inv = 1.f / red[0];

    #pragma unroll
    for (int i = 0; i < 8; i++) {
        const int idx = base + i * 256 + tid;
        const float w = l[i] * inv;
        out[ATTN_OFF + idx] = w;
        out[COV_OFF + idx]  = w + prev_cov[idx];
    }
    // zero context region for this batch (atomicAdd target in next kernel)
    for (int i = tid; i < DD; i += 256) out[CTX_OFF + b * DD + i] = 0.f;
}

// ---------------------------------------------------------------------------
// Kernel C2: context[b,d] = sum_s attn[b,s] * enc[b,s,d]
// grid (D/256=4, B=32, SSPLIT=4), 256 threads. s-split partials via atomicAdd.
// ---------------------------------------------------------------------------
__global__ void context_kernel(const float* __restrict__ enc,
                               float* __restrict__ out) {
    __shared__ float aw[512];
    const int tid = threadIdx.x;
    const int d = blockIdx.x * 256 + tid;
    const int b = blockIdx.y;
    const int sbeg = blockIdx.z * 512;

    for (int i = tid; i < 512; i += 256)
        aw[i] = out[ATTN_OFF + b * SS + sbeg + i];
    __syncthreads();

    const float* ep = enc + ((size_t)b * SS + sbeg) * DD + d;
    float a0 = 0.f, a1 = 0.f, a2 = 0.f, a3 = 0.f;
    #pragma unroll 4
    for (int s = 0; s < 512; s += 4) {
        a0 += aw[s+0] * ep[(size_t)(s+0) * DD];
        a1 += aw[s+1] * ep[(size_t)(s+1) * DD];
        a2 += aw[s+2] * ep[(size_t)(s+2) * DD];
        a3 += aw[s+3] * ep[(size_t)(s+3) * DD];
    }
    atomicAdd(&out[CTX_OFF + b * DD + d], (a0 + a1) + (a2 + a3));
}

// ---------------------------------------------------------------------------
extern "C" void kernel_launch(void* const* d_in, const int* in_sizes, int n_in,
                              void* d_out, int out_size) {
    // Input order: dec_hidden, enc_output, enc_pad_mask, [use_coverage],
    //              prev_coverage, Ws_w, Ws_b, Wh_w, Wh_b, Wc_w, Wc_b, V_w, V_b
    int base = 3;
    if (n_in > 4 && in_sizes[3] != BS) base = 4;  // skip use_coverage scalar if present

    const float* dec      = (const float*)d_in[0];
    const float* enc      = (const float*)d_in[1];
    const float* prev_cov = (const float*)d_in[base + 0];
    const float* Ws_w     = (const float*)d_in[base + 1];
    const float* Ws_b     = (const float*)d_in[base + 2];
    const float* Wh_w     = (const float*)d_in[base + 3];
    const float* Wh_b     = (const float*)d_in[base + 4];
    const float* Wc_w     = (const float*)d_in[base + 5];
    const float* Wc_b     = (const float*)d_in[base + 6];
    const float* V_w      = (const float*)d_in[base + 7];
    // V_b (base+8) unused: softmax is shift-invariant.

    float* out = (float*)d_out;

    hbias_kernel<<<dim3(UU / 256, BB), 256>>>(dec, Wh_w, Wh_b, Ws_b, Wc_b);
    score_gemm_kernel<<<dim3(UU / 128, BS / 128), 256>>>(enc, Ws_w, Wc_w, V_w, prev_cov);
    softmax_cov_kernel<<<BB, 256>>>(prev_cov, out);
    context_kernel<<<dim3(DD / 256, BB, 4), 256>>>(enc, out);
    (void)out_size;
}

// round 3
// speedup vs baseline: 1.8151x; 1.8151x over previous
#include <cuda_runtime.h>
#include <cuda_fp16.h>
#include <cstdint>

// Problem constants
#define BB 32
#define SS 2048
#define DD 1024
#define UU 1024
#define BS (BB*SS)            // 65536 tokens

// Output layout: context [B,D] | attn [B,S] | coverage [B,S]
#define CTX_OFF 0
#define ATTN_OFF (BB*DD)
#define COV_OFF  (BB*DD + BB*SS)

// Device scratch (allocation-free rule: __device__ globals)
__device__ float  g_hbias[BB*UU];          // dec@Wh + Wh_b + Ws_b + Wc_b
__device__ float  g_score[BS];             // pre-softmax scores
__device__ __half g_Xh[(size_t)BS*DD];     // enc_output in fp16 (128 MB)
__device__ __half g_Wth[UU*DD];            // Ws_w transposed+fp16: [U][D]

// ---------------------------------------------------------------------------
// helpers
// ---------------------------------------------------------------------------
__device__ __forceinline__ uint32_t smem_u32(const void* p) {
    uint32_t a;
    asm("{ .reg .u64 t; cvta.to.shared.u64 t, %1; cvt.u32.u64 %0, t; }"
        : "=r"(a) : "l"(p));
    return a;
}

__device__ __forceinline__ void cp16(uint32_t saddr, const void* g) {
    asm volatile("cp.async.cg.shared.global [%0], [%1], 16;" :: "r"(saddr), "l"(g));
}

__device__ __forceinline__ void mma_f16(float* d, const uint32_t* a, const uint32_t* b) {
    asm volatile(
        "mma.sync.aligned.m16n8k16.row.col.f32.f16.f16.f32 "
        "{%0,%1,%2,%3}, {%4,%5,%6,%7}, {%8,%9}, {%0,%1,%2,%3};\n"
        : "+f"(d[0]), "+f"(d[1]), "+f"(d[2]), "+f"(d[3])
        : "r"(a[0]), "r"(a[1]), "r"(a[2]), "r"(a[3]),
          "r"(b[0]), "r"(b[1]));
}

__device__ __forceinline__ float fast_tanh(float x) {
    // tanh(x) = 1 - 2/(exp(2x)+1); exp via ex2.approx. |rel err| ~1e-6.
    float e, r;
    asm("ex2.approx.ftz.f32 %0, %1;" : "=f"(e) : "f"(x * 2.885390081777927f));
    asm("rcp.approx.ftz.f32 %0, %1;" : "=f"(r) : "f"(e + 1.0f));
    return 1.0f - 2.0f * r;
}

// ---------------------------------------------------------------------------
// Kernel X: convert enc_output fp32 -> fp16 (vectorized, 8 elems/thread)
// ---------------------------------------------------------------------------
__global__ void convert_x_kernel(const float4* __restrict__ X4) {
    const size_t i = (size_t)blockIdx.x * 512 + threadIdx.x;  // 8388608 threads
    const float4 f0 = X4[i * 2];
    const float4 f1 = X4[i * 2 + 1];
    __half2 h0 = __float22half2_rn(make_float2(f0.x, f0.y));
    __half2 h1 = __float22half2_rn(make_float2(f0.z, f0.w));
    __half2 h2 = __float22half2_rn(make_float2(f1.x, f1.y));
    __half2 h3 = __float22half2_rn(make_float2(f1.z, f1.w));
    uint4 o;
    o.x = *(uint32_t*)&h0; o.y = *(uint32_t*)&h1;
    o.z = *(uint32_t*)&h2; o.w = *(uint32_t*)&h3;
    *(uint4*)(g_Xh + i * 8) = o;
}

// ---------------------------------------------------------------------------
// Kernel T: transpose + convert Ws_w [D,U] fp32 -> g_Wth [U,D] fp16
// ---------------------------------------------------------------------------
__global__ void transpose_w_kernel(const float* __restrict__ W) {
    __shared__ float t[32][33];
    const int bx = blockIdx.x * 32;   // u base
    const int by = blockIdx.y * 32;   // d base
    #pragma unroll
    for (int j = 0; j < 4; j++)
        t[threadIdx.y + j * 8][threadIdx.x] =
            W[(size_t)(by + threadIdx.y + j * 8) * UU + bx + threadIdx.x];
    __syncthreads();
    #pragma unroll
    for (int j = 0; j < 4; j++)
        g_Wth[(size_t)(bx + threadIdx.y + j * 8) * DD + by + threadIdx.x] =
            __float2half(t[threadIdx.x][threadIdx.y + j * 8]);
}

// ---------------------------------------------------------------------------
// Kernel A: hbias[b][u] = dec[b,:]@Wh_w[:,u] + Wh_b[u] + Ws_b[u] + Wc_b[u]
// Also zeroes g_score. grid (4, 32), 256 threads.
// ---------------------------------------------------------------------------
__global__ void hbias_kernel(const float* __restrict__ dec,
                             const float* __restrict__ Whw,
                             const float* __restrict__ Whb,
                             const float* __restrict__ Wsb,
                             const float* __restrict__ Wcb) {
    __shared__ float dh[DD];
    const int b = blockIdx.y;
    const int u = blockIdx.x * 256 + threadIdx.x;
    for (int i = threadIdx.x; i < DD; i += 256) dh[i] = dec[b*DD + i];
    __syncthreads();

    float a0 = 0.f, a1 = 0.f, a2 = 0.f, a3 = 0.f;
    #pragma unroll 4
    for (int d = 0; d < DD; d += 4) {
        a0 += dh[d+0] * Whw[(size_t)(d+0)*UU + u];
        a1 += dh[d+1] * Whw[(size_t)(d+1)*UU + u];
        a2 += dh[d+2] * Whw[(size_t)(d+2)*UU + u];
        a3 += dh[d+3] * Whw[(size_t)(d+3)*UU + u];
    }
    g_hbias[b*UU + u] = (a0 + a1) + (a2 + a3) + Whb[u] + Wsb[u] + Wcb[u];

    int gid = (blockIdx.y * 4 + blockIdx.x) * 256 + threadIdx.x;
    g_score[gid] = 0.f;
    g_score[gid + 32768] = 0.f;
}

// ---------------------------------------------------------------------------
// Kernel B: fp16 mma.sync fused score GEMM, 4-stage cp.async pipeline.
// BM=256, BN=128, BK=64 halves. 512 threads = 16 warps (4m x 4n), warp 64x32.
// grid (U/128=8 n-tiles fastest, BS/256=256 m-tiles).
// score[m] += sum_u v[u]*tanh( X@Ws + hbias + cov*wc )
// ---------------------------------------------------------------------------
#define BM 256
#define BN 128
#define BKH 64
#define ROWB 144                       // 128B data + 16B pad (bank spread)
#define A_BYTES (BM*ROWB)              // 36864
#define B_BYTES (BN*ROWB)              // 18432
#define STG (A_BYTES + B_BYTES)        // 55296
#define NST 4
#define KSTAGES 16                     // DD / BKH

#define OFF_HB  (NST*STG)              // 221184
#define OFF_WC  (OFF_HB + 512)
#define OFF_V   (OFF_WC + 512)
#define OFF_COV (OFF_V + 512)
#define OFF_SC  (OFF_COV + 1024)
#define SMEM_NEED (OFF_SC + 1024)      // 224768

__global__ void __launch_bounds__(512, 1)
score_gemm_fp16(const float* __restrict__ Wcw,
                const float* __restrict__ Vw,
                const float* __restrict__ cov) {
    extern __shared__ char sm[];
    const int tid  = threadIdx.x;
    const int lane = tid & 31;
    const int wid  = tid >> 5;
    const int wm   = wid >> 2;        // 0..3
    const int wn   = wid & 3;         // 0..3
    const int r    = lane >> 2;       // 0..7
    const int c    = lane & 3;        // 0..3

    const int n0 = blockIdx.x * BN;
    const int m0 = blockIdx.y * BM;
    const int b  = m0 >> 11;

    float* hb_s  = (float*)(sm + OFF_HB);
    float* wc_s  = (float*)(sm + OFF_WC);
    float* v_s   = (float*)(sm + OFF_V);
    float* cov_s = (float*)(sm + OFF_COV);
    float* sc_s  = (float*)(sm + OFF_SC);

    if (tid < 128) {
        hb_s[tid] = g_hbias[b * UU + n0 + tid];
        wc_s[tid] = Wcw[n0 + tid];
        v_s[tid]  = Vw[n0 + tid];
    }
    if (tid < 256) { cov_s[tid] = cov[m0 + tid]; sc_s[tid] = 0.f; }

    const uint32_t sbase = smem_u32(sm);
    const __half* Abase = g_Xh  + (size_t)m0 * DD;
    const __half* Bbase = g_Wth + (size_t)n0 * DD;

    float acc[4][4][4] = {};

    // -- pipeline: issue stages 0..2 --
    #define LOAD_STAGE(S) do {                                                \
        const uint32_t st_ = sbase + ((S) % NST) * STG;                       \
        const __half* As_ = Abase + (S) * BKH;                                \
        _Pragma("unroll")                                                     \
        for (int i_ = 0; i_ < 4; i_++) {                                      \
            int idx_ = tid + i_ * 512;                                        \
            int row_ = idx_ >> 3, ch_ = idx_ & 7;                             \
            cp16(st_ + row_ * ROWB + ch_ * 16, As_ + (size_t)row_ * DD + ch_ * 8); \
        }                                                                     \
        const __half* Bs_ = Bbase + (S) * BKH;                                \
        _Pragma("unroll")                                                     \
        for (int i_ = 0; i_ < 2; i_++) {                                      \
            int idx_ = tid + i_ * 512;                                        \
            int row_ = idx_ >> 3, ch_ = idx_ & 7;                             \
            cp16(st_ + A_BYTES + row_ * ROWB + ch_ * 16, Bs_ + (size_t)row_ * DD + ch_ * 8); \
        }                                                                     \
        asm volatile("cp.async.commit_group;" ::: "memory");                  \
    } while (0)

    LOAD_STAGE(0);
    LOAD_STAGE(1);
    LOAD_STAGE(2);

    for (int s = 0; s < KSTAGES; s++) {
        if (s + 3 < KSTAGES + 1)      // s <= K-3: 2 newer groups pending
            asm volatile("cp.async.wait_group 2;" ::: "memory");
        if (s == KSTAGES - 2)
            asm volatile("cp.async.wait_group 1;" ::: "memory");
        if (s == KSTAGES - 1)
            asm volatile("cp.async.wait_group 0;" ::: "memory");
        __syncthreads();
        if (s + 3 < KSTAGES) LOAD_STAGE(s + 3);

        const uint32_t* As32 = (const uint32_t*)(sm + (s % NST) * STG);
        const uint32_t* Bs32 = (const uint32_t*)(sm + (s % NST) * STG + A_BYTES);

        #pragma unroll
        for (int kk = 0; kk < 4; kk++) {
            const int kw = kk * 8;
            uint32_t af[4][4], bf[4][2];
            #pragma unroll
            for (int mi = 0; mi < 4; mi++) {
                const int mr = wm * 64 + mi * 16;
                af[mi][0] = As32[(mr + r    ) * 36 + kw + c];
                af[mi][1] = As32[(mr + r + 8) * 36 + kw + c];
                af[mi][2] = As32[(mr + r    ) * 36 + kw + c + 4];
                af[mi][3] = As32[(mr + r + 8) * 36 + kw + c + 4];
            }
            #pragma unroll
            for (int nj = 0; nj < 4; nj++) {
                const int nr = wn * 32 + nj * 8 + r;
                bf[nj][0] = Bs32[nr * 36 + kw + c];
                bf[nj][1] = Bs32[nr * 36 + kw + c + 4];
            }
            #pragma unroll
            for (int mi = 0; mi < 4; mi++)
                #pragma unroll
                for (int nj = 0; nj < 4; nj++)
                    mma_f16(acc[mi][nj], af[mi], bf[nj]);
        }
    }

    // Epilogue: tanh + dot with V, reduce per token row.
    // acc layout: [0]=(r,2c) [1]=(r,2c+1) [2]=(r+8,2c) [3]=(r+8,2c+1)
    #pragma unroll
    for (int mi = 0; mi < 4; mi++) {
        const int mr = wm * 64 + mi * 16 + r;
        const float cv0 = cov_s[mr], cv1 = cov_s[mr + 8];
        float s0 = 0.f, s1 = 0.f;
        #pragma unroll
        for (int nj = 0; nj < 4; nj++) {
            #pragma unroll
            for (int e = 0; e < 2; e++) {
                const int u = wn * 32 + nj * 8 + 2 * c + e;
                const float hb = hb_s[u], wc = wc_s[u], vv = v_s[u];
                s0 += vv * fast_tanh(acc[mi][nj][e]     + hb + cv0 * wc);
                s1 += vv * fast_tanh(acc[mi][nj][e + 2] + hb + cv1 * wc);
            }
        }
        s0 += __shfl_xor_sync(0xffffffffu, s0, 1);
        s0 += __shfl_xor_sync(0xffffffffu, s0, 2);
        s1 += __shfl_xor_sync(0xffffffffu, s1, 1);
        s1 += __shfl_xor_sync(0xffffffffu, s1, 2);
        if (c == 0) {
            atomicAdd(&sc_s[mr],     s0);
            atomicAdd(&sc_s[mr + 8], s1);
        }
    }
    __syncthreads();
    if (tid < 256) atomicAdd(&g_score[m0 + tid], sc_s[tid]);
}

// ---------------------------------------------------------------------------
// Kernel C1: softmax over S per batch; write attn + coverage; zero ctx region.
// ---------------------------------------------------------------------------
__global__ void softmax_cov_kernel(const float* __restrict__ prev_cov,
                                   float* __restrict__ out) {
    __shared__ float red[256];
    const int b = blockIdx.x, tid = threadIdx.x;
    const int base = b * SS;

    float l[8];
    float mx = -1e30f;
    #pragma unroll
    for (int i = 0; i < 8; i++) {
        l[i] = g_score[base + i * 256 + tid];
        mx = fmaxf(mx, l[i]);
    }
    red[tid] = mx; __syncthreads();
    for (int o = 128; o > 0; o >>= 1) {
        if (tid < o) red[tid] = fmaxf(red[tid], red[tid + o]);
        __syncthreads();
    }
    const float gmax = red[0];
    __syncthreads();

    float s = 0.f;
    #pragma unroll
    for (int i = 0; i < 8; i++) { l[i] = expf(l[i] - gmax); s += l[i]; }
    red[tid] = s; __syncthreads();
    for (int o = 128; o > 0; o >>= 1) {
        if (tid < o) red[tid] += red[tid + o];
        __syncthreads();
    }
    const float inv = 1.f / red[0];

    #pragma unroll
    for (int i = 0; i < 8; i++) {
        const int idx = base + i * 256 + tid;
        const float w = l[i] * inv;
        out[ATTN_OFF + idx] = w;
        out[COV_OFF + idx]  = w + prev_cov[idx];
    }
    for (int i = tid; i < DD; i += 256) out[CTX_OFF + b * DD + i] = 0.f;
}

// ---------------------------------------------------------------------------
// Kernel C2: context[b,d] = sum_s attn[b,s] * enc[b,s,d]   (fp32 enc, safe)
// grid (D/256=4, B=32, SSPLIT=8), 256 threads.
// ---------------------------------------------------------------------------
__global__ void context_kernel(const float* __restrict__ enc,
                               float* __restrict__ out) {
    __shared__ float aw[256];
    const int tid = threadIdx.x;
    const int d = blockIdx.x * 256 + tid;
    const int b = blockIdx.y;
    const int sbeg = blockIdx.z * 256;

    aw[tid] = out[ATTN_OFF + b * SS + sbeg + tid];
    __syncthreads();

    const float* ep = enc + ((size_t)b * SS + sbeg) * DD + d;
    float a0 = 0.f, a1 = 0.f, a2 = 0.f, a3 = 0.f;
    #pragma unroll 4
    for (int s = 0; s < 256; s += 4) {
        a0 += aw[s+0] * ep[(size_t)(s+0) * DD];
        a1 += aw[s+1] * ep[(size_t)(s+1) * DD];
        a2 += aw[s+2] * ep[(size_t)(s+2) * DD];
        a3 += aw[s+3] * ep[(size_t)(s+3) * DD];
    }
    atomicAdd(&out[CTX_OFF + b * DD + d], (a0 + a1) + (a2 + a3));
}

// ---------------------------------------------------------------------------
extern "C" void kernel_launch(void* const* d_in, const int* in_sizes, int n_in,
                              void* d_out, int out_size) {
    int base = 3;
    if (n_in > 4 && in_sizes[3] != BS) base = 4;  // skip use_coverage scalar if present

    const float* dec      = (const float*)d_in[0];
    const float* enc      = (const float*)d_in[1];
    const float* prev_cov = (const float*)d_in[base + 0];
    const float* Ws_w     = (const float*)d_in[base + 1];
    const float* Ws_b     = (const float*)d_in[base + 2];
    const float* Wh_w     = (const float*)d_in[base + 3];
    const float* Wh_b     = (const float*)d_in[base + 4];
    const float* Wc_w     = (const float*)d_in[base + 5];
    const float* Wc_b     = (const float*)d_in[base + 6];
    const float* V_w      = (const float*)d_in[base + 7];
    // V_b unused: softmax is shift-invariant.

    float* out = (float*)d_out;

    cudaFuncSetAttribute(score_gemm_fp16,
                         cudaFuncAttributeMaxDynamicSharedMemorySize, SMEM_NEED);

    convert_x_kernel<<<16384, 512>>>((const float4*)enc);
    transpose_w_kernel<<<dim3(UU / 32, DD / 32), dim3(32, 8)>>>(Ws_w);
    hbias_kernel<<<dim3(UU / 256, BB), 256>>>(dec, Wh_w, Wh_b, Ws_b, Wc_b);
    score_gemm_fp16<<<dim3(UU / BN, BS / BM), 512, SMEM_NEED>>>(Wc_w, V_w, prev_cov);
    softmax_cov_kernel<<<BB, 256>>>(prev_cov, out);
    context_kernel<<<dim3(DD / 256, BB, 8), 256>>>(enc, out);
    (void)out_size;
}

// round 4
// speedup vs baseline: 1.9379x; 1.0677x over previous
#include <cuda_runtime.h>
#include <cuda_fp16.h>
#include <cstdint>

// Problem constants
#define BB 32
#define SS 2048
#define DD 1024
#define UU 1024
#define BS (BB*SS)            // 65536 tokens

// Output layout: context [B,D] | attn [B,S] | coverage [B,S]
#define CTX_OFF 0
#define ATTN_OFF (BB*DD)
#define COV_OFF  (BB*DD + BB*SS)

// Device scratch (allocation-free rule: __device__ globals)
__device__ float  g_hbias[BB*UU];          // dec@Wh + Wh_b + Ws_b + Wc_b
__device__ float  g_score[BS];             // pre-softmax scores
__device__ __half g_Xh[(size_t)BS*DD];     // enc_output in fp16 (128 MB)
__device__ __half g_Wth[UU*DD];            // Ws_w transposed+fp16: [U][D]

// ---------------------------------------------------------------------------
// helpers
// ---------------------------------------------------------------------------
__device__ __forceinline__ uint32_t smem_u32(const void* p) {
    uint32_t a;
    asm("{ .reg .u64 t; cvta.to.shared.u64 t, %1; cvt.u32.u64 %0, t; }"
        : "=r"(a) : "l"(p));
    return a;
}

__device__ __forceinline__ void cp16(uint32_t saddr, const void* g) {
    asm volatile("cp.async.cg.shared.global [%0], [%1], 16;" :: "r"(saddr), "l"(g));
}

__device__ __forceinline__ void mma_f16(float* d, const uint32_t* a, const uint32_t* b) {
    asm volatile(
        "mma.sync.aligned.m16n8k16.row.col.f32.f16.f16.f32 "
        "{%0,%1,%2,%3}, {%4,%5,%6,%7}, {%8,%9}, {%0,%1,%2,%3};\n"
        : "+f"(d[0]), "+f"(d[1]), "+f"(d[2]), "+f"(d[3])
        : "r"(a[0]), "r"(a[1]), "r"(a[2]), "r"(a[3]),
          "r"(b[0]), "r"(b[1]));
}

__device__ __forceinline__ float fast_tanh(float x) {
    // tanh(x) = 1 - 2/(exp(2x)+1); exp via ex2.approx. |rel err| ~1e-6.
    float e, r;
    asm("ex2.approx.ftz.f32 %0, %1;" : "=f"(e) : "f"(x * 2.885390081777927f));
    asm("rcp.approx.ftz.f32 %0, %1;" : "=f"(r) : "f"(e + 1.0f));
    return 1.0f - 2.0f * r;
}

// ---------------------------------------------------------------------------
// Kernel X: convert enc_output fp32 -> fp16 (vectorized, 8 elems/thread)
// ---------------------------------------------------------------------------
__global__ void convert_x_kernel(const float4* __restrict__ X4) {
    const size_t i = (size_t)blockIdx.x * 512 + threadIdx.x;
    const float4 f0 = X4[i * 2];
    const float4 f1 = X4[i * 2 + 1];
    __half2 h0 = __float22half2_rn(make_float2(f0.x, f0.y));
    __half2 h1 = __float22half2_rn(make_float2(f0.z, f0.w));
    __half2 h2 = __float22half2_rn(make_float2(f1.x, f1.y));
    __half2 h3 = __float22half2_rn(make_float2(f1.z, f1.w));
    uint4 o;
    o.x = *(uint32_t*)&h0; o.y = *(uint32_t*)&h1;
    o.z = *(uint32_t*)&h2; o.w = *(uint32_t*)&h3;
    *(uint4*)(g_Xh + i * 8) = o;
}

// ---------------------------------------------------------------------------
// Kernel T: transpose + convert Ws_w [D,U] fp32 -> g_Wth [U,D] fp16
// ---------------------------------------------------------------------------
__global__ void transpose_w_kernel(const float* __restrict__ W) {
    __shared__ float t[32][33];
    const int bx = blockIdx.x * 32;   // u base
    const int by = blockIdx.y * 32;   // d base
    #pragma unroll
    for (int j = 0; j < 4; j++)
        t[threadIdx.y + j * 8][threadIdx.x] =
            W[(size_t)(by + threadIdx.y + j * 8) * UU + bx + threadIdx.x];
    __syncthreads();
    #pragma unroll
    for (int j = 0; j < 4; j++)
        g_Wth[(size_t)(bx + threadIdx.y + j * 8) * DD + by + threadIdx.x] =
            __float2half(t[threadIdx.x][threadIdx.y + j * 8]);
}

// ---------------------------------------------------------------------------
// Kernel A: hbias[b][u] = dec[b,:]@Wh_w[:,u] + Wh_b[u] + Ws_b[u] + Wc_b[u]
// Also zeroes g_score. grid (4, 32), 256 threads.
// ---------------------------------------------------------------------------
__global__ void hbias_kernel(const float* __restrict__ dec,
                             const float* __restrict__ Whw,
                             const float* __restrict__ Whb,
                             const float* __restrict__ Wsb,
                             const float* __restrict__ Wcb) {
    __shared__ float dh[DD];
    const int b = blockIdx.y;
    const int u = blockIdx.x * 256 + threadIdx.x;
    for (int i = threadIdx.x; i < DD; i += 256) dh[i] = dec[b*DD + i];
    __syncthreads();

    float a0 = 0.f, a1 = 0.f, a2 = 0.f, a3 = 0.f;
    #pragma unroll 4
    for (int d = 0; d < DD; d += 4) {
        a0 += dh[d+0] * Whw[(size_t)(d+0)*UU + u];
        a1 += dh[d+1] * Whw[(size_t)(d+1)*UU + u];
        a2 += dh[d+2] * Whw[(size_t)(d+2)*UU + u];
        a3 += dh[d+3] * Whw[(size_t)(d+3)*UU + u];
    }
    g_hbias[b*UU + u] = (a0 + a1) + (a2 + a3) + Whb[u] + Wsb[u] + Wcb[u];

    int gid = (blockIdx.y * 4 + blockIdx.x) * 256 + threadIdx.x;
    g_score[gid] = 0.f;
    g_score[gid + 32768] = 0.f;
}

// ---------------------------------------------------------------------------
// Kernel B: fp16 mma.sync fused score GEMM.
// BM=128, BN=256, BK=64 halves. 256 threads = 8 warps (2m x 4n), warp 64x64.
// Crossbar bytes/k = 2*BM*BN*(1/64+1/64) -> tensor-bound.
// grid (U/256=4 n fastest, BS/128=512 m).
// ---------------------------------------------------------------------------
#define BM 128
#define BN 256
#define BKH 64
#define ROWB 144                       // 128B data + 16B pad
#define A_BYTES (BM*ROWB)              // 18432
#define B_BYTES (BN*ROWB)              // 36864
#define STG (A_BYTES + B_BYTES)        // 55296
#define NST 4
#define KSTAGES 16                     // DD / BKH

#define OFF_HB  (NST*STG)              // 221184
#define OFF_WC  (OFF_HB + 1024)
#define OFF_V   (OFF_WC + 1024)
#define OFF_COV (OFF_V + 1024)
#define OFF_SC  (OFF_COV + 512)
#define SMEM_NEED (OFF_SC + 512)       // 225280

__global__ void __launch_bounds__(256, 1)
score_gemm_fp16(const float* __restrict__ Wcw,
                const float* __restrict__ Vw,
                const float* __restrict__ cov) {
    extern __shared__ char sm[];
    const int tid  = threadIdx.x;
    const int lane = tid & 31;
    const int wid  = tid >> 5;
    const int wm   = wid >> 2;        // 0..1
    const int wn   = wid & 3;         // 0..3
    const int r    = lane >> 2;       // 0..7
    const int c    = lane & 3;        // 0..3

    const int n0 = blockIdx.x * BN;
    const int m0 = blockIdx.y * BM;
    const int b  = m0 >> 11;

    float* hb_s  = (float*)(sm + OFF_HB);    // [256]
    float* wc_s  = (float*)(sm + OFF_WC);    // [256]
    float* v_s   = (float*)(sm + OFF_V);     // [256]
    float* cov_s = (float*)(sm + OFF_COV);   // [128]
    float* sc_s  = (float*)(sm + OFF_SC);    // [128]

    hb_s[tid] = g_hbias[b * UU + n0 + tid];
    wc_s[tid] = Wcw[n0 + tid];
    v_s[tid]  = Vw[n0 + tid];
    if (tid < 128) { cov_s[tid] = cov[m0 + tid]; sc_s[tid] = 0.f; }

    const uint32_t sbase = smem_u32(sm);
    const __half* Abase = g_Xh  + (size_t)m0 * DD;
    const __half* Bbase = g_Wth + (size_t)n0 * DD;

    float acc[4][8][4] = {};

    #define LOAD_STAGE(S) do {                                                \
        const uint32_t st_ = sbase + ((S) % NST) * STG;                       \
        const __half* As_ = Abase + (S) * BKH;                                \
        _Pragma("unroll")                                                     \
        for (int i_ = 0; i_ < 4; i_++) {                                      \
            int idx_ = tid + i_ * 256;                                        \
            int row_ = idx_ >> 3, ch_ = idx_ & 7;                             \
            cp16(st_ + row_ * ROWB + ch_ * 16, As_ + (size_t)row_ * DD + ch_ * 8); \
        }                                                                     \
        const __half* Bs_ = Bbase + (S) * BKH;                                \
        _Pragma("unroll")                                                     \
        for (int i_ = 0; i_ < 8; i_++) {                                      \
            int idx_ = tid + i_ * 256;                                        \
            int row_ = idx_ >> 3, ch_ = idx_ & 7;                             \
            cp16(st_ + A_BYTES + row_ * ROWB + ch_ * 16, Bs_ + (size_t)row_ * DD + ch_ * 8); \
        }                                                                     \
        asm volatile("cp.async.commit_group;" ::: "memory");                  \
    } while (0)

    LOAD_STAGE(0);
    LOAD_STAGE(1);
    LOAD_STAGE(2);

    for (int s = 0; s < KSTAGES; s++) {
        if (s <= KSTAGES - 3)
            asm volatile("cp.async.wait_group 2;" ::: "memory");
        else if (s == KSTAGES - 2)
            asm volatile("cp.async.wait_group 1;" ::: "memory");
        else
            asm volatile("cp.async.wait_group 0;" ::: "memory");
        __syncthreads();
        if (s + 3 < KSTAGES) LOAD_STAGE(s + 3);

        const uint32_t* As32 = (const uint32_t*)(sm + (s % NST) * STG);
        const uint32_t* Bs32 = (const uint32_t*)(sm + (s % NST) * STG + A_BYTES);

        #pragma unroll
        for (int kk = 0; kk < 4; kk++) {
            const int kw = kk * 8;
            uint32_t af[4][4], bf[8][2];
            #pragma unroll
            for (int mi = 0; mi < 4; mi++) {
                const int mr = wm * 64 + mi * 16;
                af[mi][0] = As32[(mr + r    ) * 36 + kw + c];
                af[mi][1] = As32[(mr + r + 8) * 36 + kw + c];
                af[mi][2] = As32[(mr + r    ) * 36 + kw + c + 4];
                af[mi][3] = As32[(mr + r + 8) * 36 + kw + c + 4];
            }
            #pragma unroll
            for (int nj = 0; nj < 8; nj++) {
                const int nr = wn * 64 + nj * 8 + r;
                bf[nj][0] = Bs32[nr * 36 + kw + c];
                bf[nj][1] = Bs32[nr * 36 + kw + c + 4];
            }
            #pragma unroll
            for (int mi = 0; mi < 4; mi++)
                #pragma unroll
                for (int nj = 0; nj < 8; nj++)
                    mma_f16(acc[mi][nj], af[mi], bf[nj]);
        }
    }

    // Epilogue: tanh + dot with V, reduce per token row.
    // acc layout: [0]=(r,2c) [1]=(r,2c+1) [2]=(r+8,2c) [3]=(r+8,2c+1)
    #pragma unroll
    for (int mi = 0; mi < 4; mi++) {
        const int mr = wm * 64 + mi * 16 + r;
        const float cv0 = cov_s[mr], cv1 = cov_s[mr + 8];
        float s0 = 0.f, s1 = 0.f;
        #pragma unroll
        for (int nj = 0; nj < 8; nj++) {
            #pragma unroll
            for (int e = 0; e < 2; e++) {
                const int u = wn * 64 + nj * 8 + 2 * c + e;
                const float hb = hb_s[u], wc = wc_s[u], vv = v_s[u];
                s0 += vv * fast_tanh(acc[mi][nj][e]     + hb + cv0 * wc);
                s1 += vv * fast_tanh(acc[mi][nj][e + 2] + hb + cv1 * wc);
            }
        }
        s0 += __shfl_xor_sync(0xffffffffu, s0, 1);
        s0 += __shfl_xor_sync(0xffffffffu, s0, 2);
        s1 += __shfl_xor_sync(0xffffffffu, s1, 1);
        s1 += __shfl_xor_sync(0xffffffffu, s1, 2);
        if (c == 0) {
            atomicAdd(&sc_s[mr],     s0);
            atomicAdd(&sc_s[mr + 8], s1);
        }
    }
    __syncthreads();
    if (tid < 128) atomicAdd(&g_score[m0 + tid], sc_s[tid]);
}

// ---------------------------------------------------------------------------
// Kernel C1: softmax over S per batch; write attn + coverage; zero ctx region.
// ---------------------------------------------------------------------------
__global__ void softmax_cov_kernel(const float* __restrict__ prev_cov,
                                   float* __restrict__ out) {
    __shared__ float red[256];
    const int b = blockIdx.x, tid = threadIdx.x;
    const int base = b * SS;

    float l[8];
    float mx = -1e30f;
    #pragma unroll
    for (int i = 0; i < 8; i++) {
        l[i] = g_score[base + i * 256 + tid];
        mx = fmaxf(mx, l[i]);
    }
    red[tid] = mx; __syncthreads();
    for (int o = 128; o > 0; o >>= 1) {
        if (tid < o) red[tid] = fmaxf(red[tid], red[tid + o]);
        __syncthreads();
    }
    const float gmax = red[0];
    __syncthreads();

    float s = 0.f;
    #pragma unroll
    for (int i = 0; i < 8; i++) { l[i] = expf(l[i] - gmax); s += l[i]; }
    red[tid] = s; __syncthreads();
    for (int o = 128; o > 0; o >>= 1) {
        if (tid < o) red[tid] += red[tid + o];
        __syncthreads();
    }
    const float inv = 1.f / red[0];

    #pragma unroll
    for (int i = 0; i < 8; i++) {
        const int idx = base + i * 256 + tid;
        const float w = l[i] * inv;
        out[ATTN_OFF + idx] = w;
        out[COV_OFF + idx]  = w + prev_cov[idx];
    }
    for (int i = tid; i < DD; i += 256) out[CTX_OFF + b * DD + i] = 0.f;
}

// ---------------------------------------------------------------------------
// Kernel C2: context[b,d] = sum_s attn[b,s] * X[b,s,d], reading fp16 g_Xh.
// Each thread owns one half2 column (2 d values).
// grid (512 half2-cols / 256 = 2, B=32, SSPLIT=8), 256 threads.
// ---------------------------------------------------------------------------
__global__ void context_kernel(float* __restrict__ out) {
    __shared__ float aw[256];
    const int tid = threadIdx.x;
    const int d2 = blockIdx.x * 256 + tid;     // half2 index 0..511
    const int b = blockIdx.y;
    const int sbeg = blockIdx.z * 256;

    aw[tid] = out[ATTN_OFF + b * SS + sbeg + tid];
    __syncthreads();

    const __half2* ep = (const __half2*)g_Xh + ((size_t)b * SS + sbeg) * (DD/2) + d2;
    float x0 = 0.f, y0 = 0.f, x1 = 0.f, y1 = 0.f;
    #pragma unroll 4
    for (int s = 0; s < 256; s += 2) {
        float2 f0 = __half22float2(ep[(size_t)(s+0) * (DD/2)]);
        float2 f1 = __half22float2(ep[(size_t)(s+1) * (DD/2)]);
        x0 += aw[s+0] * f0.x; y0 += aw[s+0] * f0.y;
        x1 += aw[s+1] * f1.x; y1 += aw[s+1] * f1.y;
    }
    atomicAdd(&out[CTX_OFF + b * DD + 2*d2    ], x0 + x1);
    atomicAdd(&out[CTX_OFF + b * DD + 2*d2 + 1], y0 + y1);
}

// ---------------------------------------------------------------------------
extern "C" void kernel_launch(void* const* d_in, const int* in_sizes, int n_in,
                              void* d_out, int out_size) {
    int base = 3;
    if (n_in > 4 && in_sizes[3] != BS) base = 4;  // skip use_coverage scalar if present

    const float* dec      = (const float*)d_in[0];
    const float* enc      = (const float*)d_in[1];
    const float* prev_cov = (const float*)d_in[base + 0];
    const float* Ws_w     = (const float*)d_in[base + 1];
    const float* Ws_b     = (const float*)d_in[base + 2];
    const float* Wh_w     = (const float*)d_in[base + 3];
    const float* Wh_b     = (const float*)d_in[base + 4];
    const float* Wc_w     = (const float*)d_in[base + 5];
    const float* Wc_b     = (const float*)d_in[base + 6];
    const float* V_w      = (const float*)d_in[base + 7];
    // V_b unused: softmax is shift-invariant.

    float* out = (float*)d_out;

    cudaFuncSetAttribute(score_gemm_fp16,
                         cudaFuncAttributeMaxDynamicSharedMemorySize, SMEM_NEED);

    convert_x_kernel<<<16384, 512>>>((const float4*)enc);
    transpose_w_kernel<<<dim3(UU / 32, DD / 32), dim3(32, 8)>>>(Ws_w);
    hbias_kernel<<<dim3(UU / 256, BB), 256>>>(dec, Wh_w, Wh_b, Ws_b, Wc_b);
    score_gemm_fp16<<<dim3(UU / BN, BS / BM), 256, SMEM_NEED>>>(Wc_w, V_w, prev_cov);
    softmax_cov_kernel<<<BB, 256>>>(prev_cov, out);
    context_kernel<<<dim3(2, BB, 8), 256>>>(out);
    (void)out_size;
}

// round 5
// speedup vs baseline: 2.1897x; 1.1300x over previous
#include <cuda_runtime.h>
#include <cuda_fp16.h>
#include <cstdint>

// Problem constants
#define BB 32
#define SS 2048
#define DD 1024
#define UU 1024
#define BS (BB*SS)            // 65536 tokens

// Output layout: context [B,D] | attn [B,S] | coverage [B,S]
#define CTX_OFF 0
#define ATTN_OFF (BB*DD)
#define COV_OFF  (BB*DD + BB*SS)

// Device scratch (allocation-free rule: __device__ globals)
__device__ float  g_hbias[BB*UU];          // dec@Wh + Wh_b + Ws_b + Wc_b
__device__ float  g_score[BS];             // pre-softmax scores
__device__ __half g_Xh[(size_t)BS*DD];     // enc_output in fp16 (128 MB)
__device__ __half g_Wth[UU*DD];            // Ws_w transposed+fp16: [U][D]

// ---------------------------------------------------------------------------
// helpers
// ---------------------------------------------------------------------------
__device__ __forceinline__ uint32_t smem_u32(const void* p) {
    uint32_t a;
    asm("{ .reg .u64 t; cvta.to.shared.u64 t, %1; cvt.u32.u64 %0, t; }"
        : "=r"(a) : "l"(p));
    return a;
}

__device__ __forceinline__ void cp16(uint32_t saddr, const void* g) {
    asm volatile("cp.async.cg.shared.global [%0], [%1], 16;" :: "r"(saddr), "l"(g));
}

__device__ __forceinline__ void ldsm4(uint32_t* r, uint32_t addr) {
    asm volatile("ldmatrix.sync.aligned.m8n8.x4.shared.b16 {%0,%1,%2,%3}, [%4];"
                 : "=r"(r[0]), "=r"(r[1]), "=r"(r[2]), "=r"(r[3]) : "r"(addr));
}

__device__ __forceinline__ void mma_f16(float* d, const uint32_t* a, const uint32_t* b) {
    asm volatile(
        "mma.sync.aligned.m16n8k16.row.col.f32.f16.f16.f32 "
        "{%0,%1,%2,%3}, {%4,%5,%6,%7}, {%8,%9}, {%0,%1,%2,%3};\n"
        : "+f"(d[0]), "+f"(d[1]), "+f"(d[2]), "+f"(d[3])
        : "r"(a[0]), "r"(a[1]), "r"(a[2]), "r"(a[3]),
          "r"(b[0]), "r"(b[1]));
}

__device__ __forceinline__ float fast_tanh(float x) {
    float e, r;
    asm("ex2.approx.ftz.f32 %0, %1;" : "=f"(e) : "f"(x * 2.885390081777927f));
    asm("rcp.approx.ftz.f32 %0, %1;" : "=f"(r) : "f"(e + 1.0f));
    return 1.0f - 2.0f * r;
}

// ---------------------------------------------------------------------------
// Kernel X: convert enc_output fp32 -> fp16 (vectorized, 8 elems/thread)
// ---------------------------------------------------------------------------
__global__ void convert_x_kernel(const float4* __restrict__ X4) {
    const size_t i = (size_t)blockIdx.x * 512 + threadIdx.x;
    const float4 f0 = X4[i * 2];
    const float4 f1 = X4[i * 2 + 1];
    __half2 h0 = __float22half2_rn(make_float2(f0.x, f0.y));
    __half2 h1 = __float22half2_rn(make_float2(f0.z, f0.w));
    __half2 h2 = __float22half2_rn(make_float2(f1.x, f1.y));
    __half2 h3 = __float22half2_rn(make_float2(f1.z, f1.w));
    uint4 o;
    o.x = *(uint32_t*)&h0; o.y = *(uint32_t*)&h1;
    o.z = *(uint32_t*)&h2; o.w = *(uint32_t*)&h3;
    *(uint4*)(g_Xh + i * 8) = o;
}

// ---------------------------------------------------------------------------
// Kernel T: transpose + convert Ws_w [D,U] fp32 -> g_Wth [U,D] fp16
// ---------------------------------------------------------------------------
__global__ void transpose_w_kernel(const float* __restrict__ W) {
    __shared__ float t[32][33];
    const int bx = blockIdx.x * 32;   // u base
    const int by = blockIdx.y * 32;   // d base
    #pragma unroll
    for (int j = 0; j < 4; j++)
        t[threadIdx.y + j * 8][threadIdx.x] =
            W[(size_t)(by + threadIdx.y + j * 8) * UU + bx + threadIdx.x];
    __syncthreads();
    #pragma unroll
    for (int j = 0; j < 4; j++)
        g_Wth[(size_t)(bx + threadIdx.y + j * 8) * DD + by + threadIdx.x] =
            __float2half(t[threadIdx.x][threadIdx.y + j * 8]);
}

// ---------------------------------------------------------------------------
// Kernel A: hbias[b][u] = dec[b,:]@Wh_w[:,u] + Wh_b[u] + Ws_b[u] + Wc_b[u]
// ---------------------------------------------------------------------------
__global__ void hbias_kernel(const float* __restrict__ dec,
                             const float* __restrict__ Whw,
                             const float* __restrict__ Whb,
                             const float* __restrict__ Wsb,
                             const float* __restrict__ Wcb) {
    __shared__ float dh[DD];
    const int b = blockIdx.y;
    const int u = blockIdx.x * 256 + threadIdx.x;
    for (int i = threadIdx.x; i < DD; i += 256) dh[i] = dec[b*DD + i];
    __syncthreads();

    float a0 = 0.f, a1 = 0.f, a2 = 0.f, a3 = 0.f;
    #pragma unroll 4
    for (int d = 0; d < DD; d += 4) {
        a0 += dh[d+0] * Whw[(size_t)(d+0)*UU + u];
        a1 += dh[d+1] * Whw[(size_t)(d+1)*UU + u];
        a2 += dh[d+2] * Whw[(size_t)(d+2)*UU + u];
        a3 += dh[d+3] * Whw[(size_t)(d+3)*UU + u];
    }
    g_hbias[b*UU + u] = (a0 + a1) + (a2 + a3) + Whb[u] + Wsb[u] + Wcb[u];

    int gid = (blockIdx.y * 4 + blockIdx.x) * 256 + threadIdx.x;
    g_score[gid] = 0.f;
    g_score[gid + 32768] = 0.f;
}

// ---------------------------------------------------------------------------
// Kernel B: fp16 mma.sync fused score GEMM, ldmatrix + XOR swizzle +
// fragment double-buffering. BM=128, BN=256, BK=64h, 8 warps (2m x 4n), 64x64.
// ---------------------------------------------------------------------------
#define BM 128
#define BN 256
#define BKH 64
#define A_BYTES (BM*128)               // 16384 (128B swizzled rows)
#define B_BYTES (BN*128)               // 32768
#define STG (A_BYTES + B_BYTES)        // 49152
#define NST 4
#define KSTAGES 16                     // DD / BKH

#define OFF_HB  (NST*STG)              // 196608
#define OFF_WC  (OFF_HB + 1024)
#define OFF_V   (OFF_WC + 1024)
#define OFF_COV (OFF_V + 1024)
#define OFF_SC  (OFF_COV + 512)
#define SMEM_NEED (OFF_SC + 512)       // 200704

__global__ void __launch_bounds__(256, 1)
score_gemm_fp16(const float* __restrict__ Wcw,
                const float* __restrict__ Vw,
                const float* __restrict__ cov) {
    extern __shared__ char sm[];
    const int tid  = threadIdx.x;
    const int lane = tid & 31;
    const int wid  = tid >> 5;
    const int wm   = wid >> 2;        // 0..1
    const int wn   = wid & 3;         // 0..3
    const int r    = lane >> 2;       // 0..7
    const int c    = lane & 3;        // 0..3

    const int n0 = blockIdx.x * BN;
    const int m0 = blockIdx.y * BM;
    const int b  = m0 >> 11;

    float* hb_s  = (float*)(sm + OFF_HB);    // [256]
    float* wc_s  = (float*)(sm + OFF_WC);    // [256]
    float* v_s   = (float*)(sm + OFF_V);     // [256]
    float* cov_s = (float*)(sm + OFF_COV);   // [128]
    float* sc_s  = (float*)(sm + OFF_SC);    // [128]

    hb_s[tid] = g_hbias[b * UU + n0 + tid];
    wc_s[tid] = Wcw[n0 + tid];
    v_s[tid]  = Vw[n0 + tid];
    if (tid < 128) { cov_s[tid] = cov[m0 + tid]; sc_s[tid] = 0.f; }

    const uint32_t sbase = smem_u32(sm);
    const __half* Abase = g_Xh  + (size_t)m0 * DD;
    const __half* Bbase = g_Wth + (size_t)n0 * DD;

    // ldmatrix per-thread invariants
    const uint32_t slane = lane & 7;
    const uint32_t ahi   = lane >> 4;           // A chunk bit
    const uint32_t bbit  = (lane >> 3) & 1;     // B chunk bit
    uint32_t arow_off[4], brow_off[4];
    #pragma unroll
    for (int mi = 0; mi < 4; mi++)
        arow_off[mi] = (uint32_t)((wm * 64 + mi * 16 + (lane & 15)) << 7);
    #pragma unroll
    for (int njp = 0; njp < 4; njp++)
        brow_off[njp] = (uint32_t)(((wn * 64 + njp * 16 + slane + (ahi << 3)) << 7)
                                   + A_BYTES);

    float acc[4][8][4] = {};

    // cp.async tile loader: XOR-swizzled 128B rows
    #define LOAD_STAGE(S) do {                                                \
        const uint32_t st_ = sbase + ((S) % NST) * STG;                       \
        const __half* As_ = Abase + (S) * BKH;                                \
        _Pragma("unroll")                                                     \
        for (int i_ = 0; i_ < 4; i_++) {                                      \
            int idx_ = tid + i_ * 256;                                        \
            int row_ = idx_ >> 3, ch_ = idx_ & 7;                             \
            cp16(st_ + (row_ << 7) + (((ch_ ^ (row_ & 7))) << 4),             \
                 As_ + (size_t)row_ * DD + ch_ * 8);                          \
        }                                                                     \
        const __half* Bs_ = Bbase + (S) * BKH;                                \
        _Pragma("unroll")                                                     \
        for (int i_ = 0; i_ < 8; i_++) {                                      \
            int idx_ = tid + i_ * 256;                                        \
            int row_ = idx_ >> 3, ch_ = idx_ & 7;                             \
            cp16(st_ + A_BYTES + (row_ << 7) + (((ch_ ^ (row_ & 7))) << 4),   \
                 Bs_ + (size_t)row_ * DD + ch_ * 8);                          \
        }                                                                     \
        asm volatile("cp.async.commit_group;" ::: "memory");                  \
    } while (0)

    // fragment loader for one kk (k = kk*16 halves)
    #define LOAD_FRAGS(ST_, KK_, AF_, BF_) do {                               \
        const uint32_t xa_ = ((((KK_) << 1) + ahi)  ^ slane) << 4;            \
        const uint32_t xb_ = ((((KK_) << 1) + bbit) ^ slane) << 4;            \
        _Pragma("unroll")                                                     \
        for (int mi_ = 0; mi_ < 4; mi_++)                                     \
            ldsm4(AF_[mi_], (ST_) + arow_off[mi_] + xa_);                     \
        _Pragma("unroll")                                                     \
        for (int nj_ = 0; nj_ < 4; nj_++)                                     \
            ldsm4(BF_[nj_], (ST_) + brow_off[nj_] + xb_);                     \
    } while (0)

    LOAD_STAGE(0);
    LOAD_STAGE(1);
    LOAD_STAGE(2);

    for (int s = 0; s < KSTAGES; s++) {
        if (s <= KSTAGES - 3)
            asm volatile("cp.async.wait_group 2;" ::: "memory");
        else if (s == KSTAGES - 2)
            asm volatile("cp.async.wait_group 1;" ::: "memory");
        else
            asm volatile("cp.async.wait_group 0;" ::: "memory");
        __syncthreads();
        if (s + 3 < KSTAGES) LOAD_STAGE(s + 3);

        const uint32_t st = sbase + (s % NST) * STG;

        uint32_t af[2][4][4], bf[2][4][4];
        LOAD_FRAGS(st, 0, af[0], bf[0]);

        #pragma unroll
        for (int kk = 0; kk < 4; kk++) {
            const int cur = kk & 1, nxt = cur ^ 1;
            if (kk < 3) LOAD_FRAGS(st, kk + 1, af[nxt], bf[nxt]);
            #pragma unroll
            for (int mi = 0; mi < 4; mi++) {
                #pragma unroll
                for (int njp = 0; njp < 4; njp++) {
                    mma_f16(acc[mi][2*njp    ], af[cur][mi], &bf[cur][njp][0]);
                    mma_f16(acc[mi][2*njp + 1], af[cur][mi], &bf[cur][njp][2]);
                }
            }
        }
    }

    // Epilogue: tanh + dot with V, reduce per token row.
    // acc[mi][nj]: n base = wn*64 + nj*8; elems: [0]=(r,2c) [1]=(r,2c+1)
    // [2]=(r+8,2c) [3]=(r+8,2c+1)
    #pragma unroll
    for (int mi = 0; mi < 4; mi++) {
        const int mr = wm * 64 + mi * 16 + r;
        const float cv0 = cov_s[mr], cv1 = cov_s[mr + 8];
        float s0 = 0.f, s1 = 0.f;
        #pragma unroll
        for (int nj = 0; nj < 8; nj++) {
            #pragma unroll
            for (int e = 0; e < 2; e++) {
                const int u = wn * 64 + nj * 8 + 2 * c + e;
                const float hb = hb_s[u], wc = wc_s[u], vv = v_s[u];
                s0 += vv * fast_tanh(acc[mi][nj][e]     + hb + cv0 * wc);
                s1 += vv * fast_tanh(acc[mi][nj][e + 2] + hb + cv1 * wc);
            }
        }
        s0 += __shfl_xor_sync(0xffffffffu, s0, 1);
        s0 += __shfl_xor_sync(0xffffffffu, s0, 2);
        s1 += __shfl_xor_sync(0xffffffffu, s1, 1);
        s1 += __shfl_xor_sync(0xffffffffu, s1, 2);
        if (c == 0) {
            atomicAdd(&sc_s[mr],     s0);
            atomicAdd(&sc_s[mr + 8], s1);
        }
    }
    __syncthreads();
    if (tid < 128) atomicAdd(&g_score[m0 + tid], sc_s[tid]);
}

// ---------------------------------------------------------------------------
// Kernel C1: softmax over S per batch; write attn + coverage; zero ctx region.
// ---------------------------------------------------------------------------
__global__ void softmax_cov_kernel(const float* __restrict__ prev_cov,
                                   float* __restrict__ out) {
    __shared__ float red[256];
    const int b = blockIdx.x, tid = threadIdx.x;
    const int base = b * SS;

    float l[8];
    float mx = -1e30f;
    #pragma unroll
    for (int i = 0; i < 8; i++) {
        l[i] = g_score[base + i * 256 + tid];
        mx = fmaxf(mx, l[i]);
    }
    red[tid] = mx; __syncthreads();
    for (int o = 128; o > 0; o >>= 1) {
        if (tid < o) red[tid] = fmaxf(red[tid], red[tid + o]);
        __syncthreads();
    }
    const float gmax = red[0];
    __syncthreads();

    float s = 0.f;
    #pragma unroll
    for (int i = 0; i < 8; i++) { l[i] = expf(l[i] - gmax); s += l[i]; }
    red[tid] = s; __syncthreads();
    for (int o = 128; o > 0; o >>= 1) {
        if (tid < o) red[tid] += red[tid + o];
        __syncthreads();
    }
    const float inv = 1.f / red[0];

    #pragma unroll
    for (int i = 0; i < 8; i++) {
        const int idx = base + i * 256 + tid;
        const float w = l[i] * inv;
        out[ATTN_OFF + idx] = w;
        out[COV_OFF + idx]  = w + prev_cov[idx];
    }
    for (int i = tid; i < DD; i += 256) out[CTX_OFF + b * DD + i] = 0.f;
}

// ---------------------------------------------------------------------------
// Kernel C2: context[b,d] = sum_s attn[b,s] * X[b,s,d], reading fp16 g_Xh.
// ---------------------------------------------------------------------------
__global__ void context_kernel(float* __restrict__ out) {
    __shared__ float aw[256];
    const int tid = threadIdx.x;
    const int d2 = blockIdx.x * 256 + tid;     // half2 index 0..511
    const int b = blockIdx.y;
    const int sbeg = blockIdx.z * 256;

    aw[tid] = out[ATTN_OFF + b * SS + sbeg + tid];
    __syncthreads();

    const __half2* ep = (const __half2*)g_Xh + ((size_t)b * SS + sbeg) * (DD/2) + d2;
    float x0 = 0.f, y0 = 0.f, x1 = 0.f, y1 = 0.f;
    #pragma unroll 4
    for (int s = 0; s < 256; s += 2) {
        float2 f0 = __half22float2(ep[(size_t)(s+0) * (DD/2)]);
        float2 f1 = __half22float2(ep[(size_t)(s+1) * (DD/2)]);
        x0 += aw[s+0] * f0.x; y0 += aw[s+0] * f0.y;
        x1 += aw[s+1] * f1.x; y1 += aw[s+1] * f1.y;
    }
    atomicAdd(&out[CTX_OFF + b * DD + 2*d2    ], x0 + x1);
    atomicAdd(&out[CTX_OFF + b * DD + 2*d2 + 1], y0 + y1);
}

// ---------------------------------------------------------------------------
extern "C" void kernel_launch(void* const* d_in, const int* in_sizes, int n_in,
                              void* d_out, int out_size) {
    int base = 3;
    if (n_in > 4 && in_sizes[3] != BS) base = 4;  // skip use_coverage scalar if present

    const float* dec      = (const float*)d_in[0];
    const float* enc      = (const float*)d_in[1];
    const float* prev_cov = (const float*)d_in[base + 0];
    const float* Ws_w     = (const float*)d_in[base + 1];
    const float* Ws_b     = (const float*)d_in[base + 2];
    const float* Wh_w     = (const float*)d_in[base + 3];
    const float* Wh_b     = (const float*)d_in[base + 4];
    const float* Wc_w     = (const float*)d_in[base + 5];
    const float* Wc_b     = (const float*)d_in[base + 6];
    const float* V_w      = (const float*)d_in[base + 7];
    // V_b unused: softmax is shift-invariant.

    float* out = (float*)d_out;

    cudaFuncSetAttribute(score_gemm_fp16,
                         cudaFuncAttributeMaxDynamicSharedMemorySize, SMEM_NEED);

    convert_x_kernel<<<16384, 512>>>((const float4*)enc);
    transpose_w_kernel<<<dim3(UU / 32, DD / 32), dim3(32, 8)>>>(Ws_w);
    hbias_kernel<<<dim3(UU / 256, BB), 256>>>(dec, Wh_w, Wh_b, Ws_b, Wc_b);
    score_gemm_fp16<<<dim3(UU / BN, BS / BM), 256, SMEM_NEED>>>(Wc_w, V_w, prev_cov);
    softmax_cov_kernel<<<BB, 256>>>(prev_cov, out);
    context_kernel<<<dim3(2, BB, 8), 256>>>(out);
    (void)out_size;
}

// round 6
// speedup vs baseline: 2.2048x; 1.0069x over previous
#include <cuda_runtime.h>
#include <cuda_fp16.h>
#include <cstdint>

// Problem constants
#define BB 32
#define SS 2048
#define DD 1024
#define UU 1024
#define BS (BB*SS)            // 65536 tokens

// Output layout: context [B,D] | attn [B,S] | coverage [B,S]
#define CTX_OFF 0
#define ATTN_OFF (BB*DD)
#define COV_OFF  (BB*DD + BB*SS)

// Device scratch (allocation-free rule: __device__ globals)
__device__ float  g_hbias[BB*UU];          // dec@Wh + Wh_b + Ws_b + Wc_b
__device__ float  g_score[BS];             // pre-softmax scores
__device__ __half g_Xh[(size_t)BS*DD];     // enc_output in fp16 (128 MB)
__device__ __half g_Wth[UU*DD];            // Ws_w transposed+fp16: [U][D]

// ---------------------------------------------------------------------------
// helpers
// ---------------------------------------------------------------------------
__device__ __forceinline__ uint32_t smem_u32(const void* p) {
    uint32_t a;
    asm("{ .reg .u64 t; cvta.to.shared.u64 t, %1; cvt.u32.u64 %0, t; }"
        : "=r"(a) : "l"(p));
    return a;
}

__device__ __forceinline__ void cp16(uint32_t saddr, const void* g) {
    asm volatile("cp.async.cg.shared.global [%0], [%1], 16;" :: "r"(saddr), "l"(g));
}

__device__ __forceinline__ void ldsm4(uint32_t* r, uint32_t addr) {
    asm volatile("ldmatrix.sync.aligned.m8n8.x4.shared.b16 {%0,%1,%2,%3}, [%4];"
                 : "=r"(r[0]), "=r"(r[1]), "=r"(r[2]), "=r"(r[3]) : "r"(addr));
}

__device__ __forceinline__ void mma_f16(float* d, const uint32_t* a, const uint32_t* b) {
    asm volatile(
        "mma.sync.aligned.m16n8k16.row.col.f32.f16.f16.f32 "
        "{%0,%1,%2,%3}, {%4,%5,%6,%7}, {%8,%9}, {%0,%1,%2,%3};\n"
        : "+f"(d[0]), "+f"(d[1]), "+f"(d[2]), "+f"(d[3])
        : "r"(a[0]), "r"(a[1]), "r"(a[2]), "r"(a[3]),
          "r"(b[0]), "r"(b[1]));
}

__device__ __forceinline__ float fast_tanh(float x) {
    float e, r;
    asm("ex2.approx.ftz.f32 %0, %1;" : "=f"(e) : "f"(x * 2.885390081777927f));
    asm("rcp.approx.ftz.f32 %0, %1;" : "=f"(r) : "f"(e + 1.0f));
    return 1.0f - 2.0f * r;
}

// ---------------------------------------------------------------------------
// Kernel X: convert enc_output fp32 -> fp16 (vectorized, 8 elems/thread)
// ---------------------------------------------------------------------------
__global__ void convert_x_kernel(const float4* __restrict__ X4) {
    const size_t i = (size_t)blockIdx.x * 512 + threadIdx.x;
    const float4 f0 = X4[i * 2];
    const float4 f1 = X4[i * 2 + 1];
    __half2 h0 = __float22half2_rn(make_float2(f0.x, f0.y));
    __half2 h1 = __float22half2_rn(make_float2(f0.z, f0.w));
    __half2 h2 = __float22half2_rn(make_float2(f1.x, f1.y));
    __half2 h3 = __float22half2_rn(make_float2(f1.z, f1.w));
    uint4 o;
    o.x = *(uint32_t*)&h0; o.y = *(uint32_t*)&h1;
    o.z = *(uint32_t*)&h2; o.w = *(uint32_t*)&h3;
    *(uint4*)(g_Xh + i * 8) = o;
}

// ---------------------------------------------------------------------------
// Kernel T: transpose + convert Ws_w [D,U] fp32 -> g_Wth [U,D] fp16
// ---------------------------------------------------------------------------
__global__ void transpose_w_kernel(const float* __restrict__ W) {
    __shared__ float t[32][33];
    const int bx = blockIdx.x * 32;   // u base
    const int by = blockIdx.y * 32;   // d base
    #pragma unroll
    for (int j = 0; j < 4; j++)
        t[threadIdx.y + j * 8][threadIdx.x] =
            W[(size_t)(by + threadIdx.y + j * 8) * UU + bx + threadIdx.x];
    __syncthreads();
    #pragma unroll
    for (int j = 0; j < 4; j++)
        g_Wth[(size_t)(bx + threadIdx.y + j * 8) * DD + by + threadIdx.x] =
            __float2half(t[threadIdx.x][threadIdx.y + j * 8]);
}

// ---------------------------------------------------------------------------
// Kernel A: hbias[b][u] = dec[b,:]@Wh_w[:,u] + Wh_b[u] + Ws_b[u] + Wc_b[u]
// ---------------------------------------------------------------------------
__global__ void hbias_kernel(const float* __restrict__ dec,
                             const float* __restrict__ Whw,
                             const float* __restrict__ Whb,
                             const float* __restrict__ Wsb,
                             const float* __restrict__ Wcb) {
    __shared__ float dh[DD];
    const int b = blockIdx.y;
    const int u = blockIdx.x * 256 + threadIdx.x;
    for (int i = threadIdx.x; i < DD; i += 256) dh[i] = dec[b*DD + i];
    __syncthreads();

    float a0 = 0.f, a1 = 0.f, a2 = 0.f, a3 = 0.f;
    #pragma unroll 4
    for (int d = 0; d < DD; d += 4) {
        a0 += dh[d+0] * Whw[(size_t)(d+0)*UU + u];
        a1 += dh[d+1] * Whw[(size_t)(d+1)*UU + u];
        a2 += dh[d+2] * Whw[(size_t)(d+2)*UU + u];
        a3 += dh[d+3] * Whw[(size_t)(d+3)*UU + u];
    }
    g_hbias[b*UU + u] = (a0 + a1) + (a2 + a3) + Whb[u] + Wsb[u] + Wcb[u];

    int gid = (blockIdx.y * 4 + blockIdx.x) * 256 + threadIdx.x;
    g_score[gid] = 0.f;
    g_score[gid + 32768] = 0.f;
}

// ---------------------------------------------------------------------------
// Kernel B: fp16 mma.sync fused score GEMM, ldmatrix + XOR swizzle.
// BM=256, BN=128, BK=64h. 512 threads = 16 warps (4m x 4n), warp 64x32.
// 4 warps/SMSP for latency hiding; acc 64 regs/thread.
// grid (U/128=8 n fastest, BS/256=256 m).
// ---------------------------------------------------------------------------
#define BM 256
#define BN 128
#define BKH 64
#define A_BYTES (BM*128)               // 32768 (128B swizzled rows)
#define B_BYTES (BN*128)               // 16384
#define STG (A_BYTES + B_BYTES)        // 49152
#define NST 4
#define KSTAGES 16                     // DD / BKH

#define OFF_HB  (NST*STG)              // 196608
#define OFF_WC  (OFF_HB + 512)
#define OFF_V   (OFF_WC + 512)
#define OFF_COV (OFF_V + 512)
#define OFF_SC  (OFF_COV + 1024)
#define SMEM_NEED (OFF_SC + 1024)      // 200192

__global__ void __launch_bounds__(512, 1)
score_gemm_fp16(const float* __restrict__ Wcw,
                const float* __restrict__ Vw,
                const float* __restrict__ cov) {
    extern __shared__ char sm[];
    const int tid  = threadIdx.x;
    const int lane = tid & 31;
    const int wid  = tid >> 5;
    const int wm   = wid >> 2;        // 0..3
    const int wn   = wid & 3;         // 0..3
    const int r    = lane >> 2;       // 0..7
    const int c    = lane & 3;        // 0..3

    const int n0 = blockIdx.x * BN;
    const int m0 = blockIdx.y * BM;
    const int b  = m0 >> 11;

    float* hb_s  = (float*)(sm + OFF_HB);    // [128]
    float* wc_s  = (float*)(sm + OFF_WC);    // [128]
    float* v_s   = (float*)(sm + OFF_V);     // [128]
    float* cov_s = (float*)(sm + OFF_COV);   // [256]
    float* sc_s  = (float*)(sm + OFF_SC);    // [256]

    if (tid < 128) {
        hb_s[tid] = g_hbias[b * UU + n0 + tid];
        wc_s[tid] = Wcw[n0 + tid];
        v_s[tid]  = Vw[n0 + tid];
    }
    if (tid < 256) { cov_s[tid] = cov[m0 + tid]; sc_s[tid] = 0.f; }

    const uint32_t sbase = smem_u32(sm);
    const __half* Abase = g_Xh  + (size_t)m0 * DD;
    const __half* Bbase = g_Wth + (size_t)n0 * DD;

    // ldmatrix per-thread invariants
    const uint32_t slane = lane & 7;
    const uint32_t ahi   = lane >> 4;           // A chunk bit
    const uint32_t bbit  = (lane >> 3) & 1;     // B chunk bit
    uint32_t arow_off[4], brow_off[2];
    #pragma unroll
    for (int mi = 0; mi < 4; mi++)
        arow_off[mi] = (uint32_t)((wm * 64 + mi * 16 + (lane & 15)) << 7);
    #pragma unroll
    for (int njp = 0; njp < 2; njp++)
        brow_off[njp] = (uint32_t)(((wn * 32 + njp * 16 + slane + (ahi << 3)) << 7)
                                   + A_BYTES);

    float acc[4][4][4] = {};

    // cp.async tile loader: XOR-swizzled 128B rows
    #define LOAD_STAGE(S) do {                                                \
        const uint32_t st_ = sbase + ((S) % NST) * STG;                       \
        const __half* As_ = Abase + (S) * BKH;                                \
        _Pragma("unroll")                                                     \
        for (int i_ = 0; i_ < 4; i_++) {                                      \
            int idx_ = tid + i_ * 512;                                        \
            int row_ = idx_ >> 3, ch_ = idx_ & 7;                             \
            cp16(st_ + (row_ << 7) + (((ch_ ^ (row_ & 7))) << 4),             \
                 As_ + (size_t)row_ * DD + ch_ * 8);                          \
        }                                                                     \
        const __half* Bs_ = Bbase + (S) * BKH;                                \
        _Pragma("unroll")                                                     \
        for (int i_ = 0; i_ < 2; i_++) {                                      \
            int idx_ = tid + i_ * 512;                                        \
            int row_ = idx_ >> 3, ch_ = idx_ & 7;                             \
            cp16(st_ + A_BYTES + (row_ << 7) + (((ch_ ^ (row_ & 7))) << 4),   \
                 Bs_ + (size_t)row_ * DD + ch_ * 8);                          \
        }                                                                     \
        asm volatile("cp.async.commit_group;" ::: "memory");                  \
    } while (0)

    // fragment loader for one kk (k = kk*16 halves)
    #define LOAD_FRAGS(ST_, KK_, AF_, BF_) do {                               \
        const uint32_t xa_ = ((((KK_) << 1) + ahi)  ^ slane) << 4;            \
        const uint32_t xb_ = ((((KK_) << 1) + bbit) ^ slane) << 4;            \
        _Pragma("unroll")                                                     \
        for (int mi_ = 0; mi_ < 4; mi_++)                                     \
            ldsm4(AF_[mi_], (ST_) + arow_off[mi_] + xa_);                     \
        _Pragma("unroll")                                                     \
        for (int nj_ = 0; nj_ < 2; nj_++)                                     \
            ldsm4(BF_[nj_], (ST_) + brow_off[nj_] + xb_);                     \
    } while (0)

    LOAD_STAGE(0);
    LOAD_STAGE(1);
    LOAD_STAGE(2);

    for (int s = 0; s < KSTAGES; s++) {
        if (s <= KSTAGES - 3)
            asm volatile("cp.async.wait_group 2;" ::: "memory");
        else if (s == KSTAGES - 2)
            asm volatile("cp.async.wait_group 1;" ::: "memory");
        else
            asm volatile("cp.async.wait_group 0;" ::: "memory");
        __syncthreads();
        if (s + 3 < KSTAGES) LOAD_STAGE(s + 3);

        const uint32_t st = sbase + (s % NST) * STG;

        uint32_t af[2][4][4], bf[2][2][4];
        LOAD_FRAGS(st, 0, af[0], bf[0]);

        #pragma unroll
        for (int kk = 0; kk < 4; kk++) {
            const int cur = kk & 1, nxt = cur ^ 1;
            if (kk < 3) LOAD_FRAGS(st, kk + 1, af[nxt], bf[nxt]);
            #pragma unroll
            for (int mi = 0; mi < 4; mi++) {
                #pragma unroll
                for (int njp = 0; njp < 2; njp++) {
                    mma_f16(acc[mi][2*njp    ], af[cur][mi], &bf[cur][njp][0]);
                    mma_f16(acc[mi][2*njp + 1], af[cur][mi], &bf[cur][njp][2]);
                }
            }
        }
    }

    // Epilogue: tanh + dot with V, reduce per token row.
    // acc[mi][nj]: n base = wn*32 + nj*8; elems: [0]=(r,2c) [1]=(r,2c+1)
    // [2]=(r+8,2c) [3]=(r+8,2c+1)
    #pragma unroll
    for (int mi = 0; mi < 4; mi++) {
        const int mr = wm * 64 + mi * 16 + r;
        const float cv0 = cov_s[mr], cv1 = cov_s[mr + 8];
        float s0 = 0.f, s1 = 0.f;
        #pragma unroll
        for (int nj = 0; nj < 4; nj++) {
            #pragma unroll
            for (int e = 0; e < 2; e++) {
                const int u = wn * 32 + nj * 8 + 2 * c + e;
                const float hb = hb_s[u], wc = wc_s[u], vv = v_s[u];
                s0 += vv * fast_tanh(acc[mi][nj][e]     + hb + cv0 * wc);
                s1 += vv * fast_tanh(acc[mi][nj][e + 2] + hb + cv1 * wc);
            }
        }
        s0 += __shfl_xor_sync(0xffffffffu, s0, 1);
        s0 += __shfl_xor_sync(0xffffffffu, s0, 2);
        s1 += __shfl_xor_sync(0xffffffffu, s1, 1);
        s1 += __shfl_xor_sync(0xffffffffu, s1, 2);
        if (c == 0) {
            atomicAdd(&sc_s[mr],     s0);
            atomicAdd(&sc_s[mr + 8], s1);
        }
    }
    __syncthreads();
    if (tid < 256) atomicAdd(&g_score[m0 + tid], sc_s[tid]);
}

// ---------------------------------------------------------------------------
// Kernel C1: softmax over S per batch; write attn + coverage; zero ctx region.
// ---------------------------------------------------------------------------
__global__ void softmax_cov_kernel(const float* __restrict__ prev_cov,
                                   float* __restrict__ out) {
    __shared__ float red[256];
    const int b = blockIdx.x, tid = threadIdx.x;
    const int base = b * SS;

    float l[8];
    float mx = -1e30f;
    #pragma unroll
    for (int i = 0; i < 8; i++) {
        l[i] = g_score[base + i * 256 + tid];
        mx = fmaxf(mx, l[i]);
    }
    red[tid] = mx; __syncthreads();
    for (int o = 128; o > 0; o >>= 1) {
        if (tid < o) red[tid] = fmaxf(red[tid], red[tid + o]);
        __syncthreads();
    }
    const float gmax = red[0];
    __syncthreads();

    float s = 0.f;
    #pragma unroll
    for (int i = 0; i < 8; i++) { l[i] = expf(l[i] - gmax); s += l[i]; }
    red[tid] = s; __syncthreads();
    for (int o = 128; o > 0; o >>= 1) {
        if (tid < o) red[tid] += red[tid + o];
        __syncthreads();
    }
    const float inv = 1.f / red[0];

    #pragma unroll
    for (int i = 0; i < 8; i++) {
        const int idx = base + i * 256 + tid;
        const float w = l[i] * inv;
        out[ATTN_OFF + idx] = w;
        out[COV_OFF + idx]  = w + prev_cov[idx];
    }
    for (int i = tid; i < DD; i += 256) out[CTX_OFF + b * DD + i] = 0.f;
}

// ---------------------------------------------------------------------------
// Kernel C2: context[b,d] = sum_s attn[b,s] * X[b,s,d], reading fp16 g_Xh.
// ---------------------------------------------------------------------------
__global__ void context_kernel(float* __restrict__ out) {
    __shared__ float aw[256];
    const int tid = threadIdx.x;
    const int d2 = blockIdx.x * 256 + tid;     // half2 index 0..511
    const int b = blockIdx.y;
    const int sbeg = blockIdx.z * 256;

    aw[tid] = out[ATTN_OFF + b * SS + sbeg + tid];
    __syncthreads();

    const __half2* ep = (const __half2*)g_Xh + ((size_t)b * SS + sbeg) * (DD/2) + d2;
    float x0 = 0.f, y0 = 0.f, x1 = 0.f, y1 = 0.f;
    #pragma unroll 4
    for (int s = 0; s < 256; s += 2) {
        float2 f0 = __half22float2(ep[(size_t)(s+0) * (DD/2)]);
        float2 f1 = __half22float2(ep[(size_t)(s+1) * (DD/2)]);
        x0 += aw[s+0] * f0.x; y0 += aw[s+0] * f0.y;
        x1 += aw[s+1] * f1.x; y1 += aw[s+1] * f1.y;
    }
    atomicAdd(&out[CTX_OFF + b * DD + 2*d2    ], x0 + x1);
    atomicAdd(&out[CTX_OFF + b * DD + 2*d2 + 1], y0 + y1);
}

// ---------------------------------------------------------------------------
extern "C" void kernel_launch(void* const* d_in, const int* in_sizes, int n_in,
                              void* d_out, int out_size) {
    int base = 3;
    if (n_in > 4 && in_sizes[3] != BS) base = 4;  // skip use_coverage scalar if present

    const float* dec      = (const float*)d_in[0];
    const float* enc      = (const float*)d_in[1];
    const float* prev_cov = (const float*)d_in[base + 0];
    const float* Ws_w     = (const float*)d_in[base + 1];
    const float* Ws_b     = (const float*)d_in[base + 2];
    const float* Wh_w     = (const float*)d_in[base + 3];
    const float* Wh_b     = (const float*)d_in[base + 4];
    const float* Wc_w     = (const float*)d_in[base + 5];
    const float* Wc_b     = (const float*)d_in[base + 6];
    const float* V_w      = (const float*)d_in[base + 7];
    // V_b unused: softmax is shift-invariant.

    float* out = (float*)d_out;

    cudaFuncSetAttribute(score_gemm_fp16,
                         cudaFuncAttributeMaxDynamicSharedMemorySize, SMEM_NEED);

    convert_x_kernel<<<16384, 512>>>((const float4*)enc);
    transpose_w_kernel<<<dim3(UU / 32, DD / 32), dim3(32, 8)>>>(Ws_w);
    hbias_kernel<<<dim3(UU / 256, BB), 256>>>(dec, Wh_w, Wh_b, Ws_b, Wc_b);
    score_gemm_fp16<<<dim3(UU / BN, BS / BM), 512, SMEM_NEED>>>(Wc_w, V_w, prev_cov);
    softmax_cov_kernel<<<BB, 256>>>(prev_cov, out);
    context_kernel<<<dim3(2, BB, 8), 256>>>(out);
    (void)out_size;
}

// round 7
// speedup vs baseline: 2.2065x; 1.0008x over previous
#include <cuda_runtime.h>
#include <cuda_fp16.h>
#include <cstdint>

// Problem constants
#define BB 32
#define SS 2048
#define DD 1024
#define UU 1024
#define BS (BB*SS)            // 65536 tokens

// Output layout: context [B,D] | attn [B,S] | coverage [B,S]
#define CTX_OFF 0
#define ATTN_OFF (BB*DD)
#define COV_OFF  (BB*DD + BB*SS)

// GEMM tiling
#define BM 256
#define BN 128
#define BKH 64                         // K-chunk in halves (128B rows)
#define KSTAGES 16                     // DD / BKH
#define A_BLK_H 16384                  // halves per A tile block (256*64) = 32KB
#define B_BLK_H 8192                   // halves per B tile block (128*64) = 16KB

// Device scratch (allocation-free rule: __device__ globals)
__device__ float  g_hbias[BB*UU];          // dec@Wh + Wh_b + Ws_b + Wc_b
__device__ float  g_score[BS];             // pre-softmax scores
__device__ __half g_Xh[(size_t)BS*DD];     // enc_output fp16, tile-blocked+swizzled
__device__ __half g_Wth[UU*DD];            // Ws_w^T fp16, tile-blocked+swizzled

// ---------------------------------------------------------------------------
// helpers
// ---------------------------------------------------------------------------
__device__ __forceinline__ uint32_t smem_u32(const void* p) {
    uint32_t a;
    asm("{ .reg .u64 t; cvta.to.shared.u64 t, %1; cvt.u32.u64 %0, t; }"
        : "=r"(a) : "l"(p));
    return a;
}

__device__ __forceinline__ void mbar_init(uint32_t addr, uint32_t cnt) {
    asm volatile("mbarrier.init.shared.b64 [%0], %1;" :: "r"(addr), "r"(cnt) : "memory");
}

__device__ __forceinline__ void mbar_expect_tx(uint32_t addr, uint32_t bytes) {
    asm volatile("mbarrier.arrive.expect_tx.shared.b64 _, [%0], %1;"
                 :: "r"(addr), "r"(bytes) : "memory");
}

__device__ __forceinline__ void mbar_wait(uint32_t addr, uint32_t parity) {
    asm volatile(
        "{\n\t.reg .pred P;\n"
        "WAIT_%=: \n\t"
        "mbarrier.try_wait.parity.acquire.cta.shared::cta.b64 P, [%0], %1, 0x989680;\n\t"
        "@P bra DONE_%=;\n\t"
        "bra WAIT_%=;\n"
        "DONE_%=: \n\t}"
        :: "r"(addr), "r"(parity) : "memory");
}

__device__ __forceinline__ void bulk_ld(uint32_t sdst, const void* gsrc,
                                        uint32_t bytes, uint32_t mbar) {
    asm volatile(
        "cp.async.bulk.shared::cta.global.mbarrier::complete_tx::bytes "
        "[%0], [%1], %2, [%3];"
        :: "r"(sdst), "l"(gsrc), "r"(bytes), "r"(mbar) : "memory");
}

__device__ __forceinline__ void fence_proxy_async_cta() {
    asm volatile("fence.proxy.async.shared::cta;" ::: "memory");
}

__device__ __forceinline__ void ldsm4(uint32_t* r, uint32_t addr) {
    asm volatile("ldmatrix.sync.aligned.m8n8.x4.shared.b16 {%0,%1,%2,%3}, [%4];"
                 : "=r"(r[0]), "=r"(r[1]), "=r"(r[2]), "=r"(r[3]) : "r"(addr));
}

__device__ __forceinline__ void mma_f16(float* d, const uint32_t* a, const uint32_t* b) {
    asm volatile(
        "mma.sync.aligned.m16n8k16.row.col.f32.f16.f16.f32 "
        "{%0,%1,%2,%3}, {%4,%5,%6,%7}, {%8,%9}, {%0,%1,%2,%3};\n"
        : "+f"(d[0]), "+f"(d[1]), "+f"(d[2]), "+f"(d[3])
        : "r"(a[0]), "r"(a[1]), "r"(a[2]), "r"(a[3]),
          "r"(b[0]), "r"(b[1]));
}

__device__ __forceinline__ float fast_tanh(float x) {
    float e, r;
    asm("ex2.approx.ftz.f32 %0, %1;" : "=f"(e) : "f"(x * 2.885390081777927f));
    asm("rcp.approx.ftz.f32 %0, %1;" : "=f"(r) : "f"(e + 1.0f));
    return 1.0f - 2.0f * r;
}

// ---------------------------------------------------------------------------
// Kernel X: convert enc fp32 -> fp16 into tile-blocked swizzled layout.
// Block (mt, kt): 256 rows x 64 halves (32KB contiguous), 128B rows with
// 16B-chunk XOR swizzle: off = (row<<7) + ((ch ^ (row&7))<<4).
// One thread per 16B output chunk; grid 16384 x 512.
// ---------------------------------------------------------------------------
__global__ void convert_x_kernel(const float* __restrict__ X) {
    const size_t i = (size_t)blockIdx.x * 512 + threadIdx.x;  // 8.39M chunks
    const int m  = (int)(i >> 7);       // token row
    const int cg = (int)(i & 127);      // chunk-in-row
    const int kt = cg >> 3;
    const int ch = cg & 7;
    const int mt = m >> 8;
    const int row = m & 255;

    const float4* src = (const float4*)(X + (size_t)m * DD + kt * 64 + ch * 8);
    const float4 f0 = src[0];
    const float4 f1 = src[1];
    __half2 h0 = __float22half2_rn(make_float2(f0.x, f0.y));
    __half2 h1 = __float22half2_rn(make_float2(f0.z, f0.w));
    __half2 h2 = __float22half2_rn(make_float2(f1.x, f1.y));
    __half2 h3 = __float22half2_rn(make_float2(f1.z, f1.w));
    uint4 o;
    o.x = *(uint32_t*)&h0; o.y = *(uint32_t*)&h1;
    o.z = *(uint32_t*)&h2; o.w = *(uint32_t*)&h3;

    char* blk = (char*)(g_Xh + ((size_t)mt * KSTAGES + kt) * A_BLK_H);
    *(uint4*)(blk + (row << 7) + ((ch ^ (row & 7)) << 4)) = o;
}

// ---------------------------------------------------------------------------
// Kernel T: transpose + convert Ws_w [D,U] fp32 -> g_Wth tile-blocked swizzled.
// Block (nt, kt): 128 rows(u) x 64 halves (16KB), same row swizzle.
// ---------------------------------------------------------------------------
__global__ void transpose_w_kernel(const float* __restrict__ W) {
    __shared__ float t[32][33];
    const int bx = blockIdx.x * 32;   // u base
    const int by = blockIdx.y * 32;   // d base
    #pragma unroll
    for (int j = 0; j < 4; j++)
        t[threadIdx.y + j * 8][threadIdx.x] =
            W[(size_t)(by + threadIdx.y + j * 8) * UU + bx + threadIdx.x];
    __syncthreads();
    #pragma unroll
    for (int j = 0; j < 4; j++) {
        const int u = bx + threadIdx.y + j * 8;
        const int d = by + threadIdx.x;
        const int nt = u >> 7, rowB = u & 127;
        const int kt = d >> 6, ch = (d & 63) >> 3, pos = d & 7;
        char* blk = (char*)(g_Wth + ((size_t)nt * KSTAGES + kt) * B_BLK_H);
        *(__half*)(blk + (rowB << 7) + ((ch ^ (rowB & 7)) << 4) + pos * 2) =
            __float2half(t[threadIdx.x][threadIdx.y + j * 8]);
    }
}

// ---------------------------------------------------------------------------
// Kernel A: hbias[b][u] = dec[b,:]@Wh_w[:,u] + Wh_b[u] + Ws_b[u] + Wc_b[u]
// ---------------------------------------------------------------------------
__global__ void hbias_kernel(const float* __restrict__ dec,
                             const float* __restrict__ Whw,
                             const float* __restrict__ Whb,
                             const float* __restrict__ Wsb,
                             const float* __restrict__ Wcb) {
    __shared__ float dh[DD];
    const int b = blockIdx.y;
    const int u = blockIdx.x * 256 + threadIdx.x;
    for (int i = threadIdx.x; i < DD; i += 256) dh[i] = dec[b*DD + i];
    __syncthreads();

    float a0 = 0.f, a1 = 0.f, a2 = 0.f, a3 = 0.f;
    #pragma unroll 4
    for (int d = 0; d < DD; d += 4) {
        a0 += dh[d+0] * Whw[(size_t)(d+0)*UU + u];
        a1 += dh[d+1] * Whw[(size_t)(d+1)*UU + u];
        a2 += dh[d+2] * Whw[(size_t)(d+2)*UU + u];
        a3 += dh[d+3] * Whw[(size_t)(d+3)*UU + u];
    }
    g_hbias[b*UU + u] = (a0 + a1) + (a2 + a3) + Whb[u] + Wsb[u] + Wcb[u];

    int gid = (blockIdx.y * 4 + blockIdx.x) * 256 + threadIdx.x;
    g_score[gid] = 0.f;
    g_score[gid + 32768] = 0.f;
}

// ---------------------------------------------------------------------------
// Kernel B: fp16 mma.sync fused score GEMM, cp.async.bulk + mbarrier pipeline.
// BM=256, BN=128, BKH=64. 512 threads = 16 warps (4m x 4n), warp 64x32.
// Stage = A block 32KB + B block 16KB, loaded with 2 bulk ops by thread 0.
// ---------------------------------------------------------------------------
#define NST 4
#define STG 49152                      // 32KB A + 16KB B
#define STG_A 32768
#define OFF_HB   (NST*STG)             // 196608
#define OFF_WC   (OFF_HB + 512)
#define OFF_V    (OFF_WC + 512)
#define OFF_COV  (OFF_V + 512)
#define OFF_SC   (OFF_COV + 1024)
#define OFF_MBAR (OFF_SC + 1024)       // 4 mbarriers
#define SMEM_NEED (OFF_MBAR + 64)      // 200256

__global__ void __launch_bounds__(512, 1)
score_gemm_fp16(const float* __restrict__ Wcw,
                const float* __restrict__ Vw,
                const float* __restrict__ cov) {
    extern __shared__ char sm[];
    const int tid  = threadIdx.x;
    const int lane = tid & 31;
    const int wid  = tid >> 5;
    const int wm   = wid >> 2;        // 0..3
    const int wn   = wid & 3;         // 0..3
    const int r    = lane >> 2;       // 0..7
    const int c    = lane & 3;        // 0..3

    const int n0 = blockIdx.x * BN;
    const int m0 = blockIdx.y * BM;
    const int b  = m0 >> 11;

    float* hb_s  = (float*)(sm + OFF_HB);    // [128]
    float* wc_s  = (float*)(sm + OFF_WC);    // [128]
    float* v_s   = (float*)(sm + OFF_V);     // [128]
    float* cov_s = (float*)(sm + OFF_COV);   // [256]
    float* sc_s  = (float*)(sm + OFF_SC);    // [256]

    const uint32_t sbase = smem_u32(sm);
    const uint32_t mb    = sbase + OFF_MBAR;

    if (tid == 0) {
        #pragma unroll
        for (int p = 0; p < NST; p++) mbar_init(mb + p * 8, 1);
    }
    __syncthreads();
    fence_proxy_async_cta();

    const __half* Ablk = g_Xh  + (size_t)blockIdx.y * KSTAGES * A_BLK_H;
    const __half* Bblk = g_Wth + (size_t)blockIdx.x * KSTAGES * B_BLK_H;

    // prologue: issue stages 0..2
    if (tid == 0) {
        #pragma unroll
        for (int p = 0; p < 3; p++) {
            mbar_expect_tx(mb + p * 8, STG);
            bulk_ld(sbase + p * STG,         Ablk + (size_t)p * A_BLK_H, STG_A, mb + p * 8);
            bulk_ld(sbase + p * STG + STG_A, Bblk + (size_t)p * B_BLK_H, STG - STG_A, mb + p * 8);
        }
    }

    if (tid < 128) {
        hb_s[tid] = g_hbias[b * UU + n0 + tid];
        wc_s[tid] = Wcw[n0 + tid];
        v_s[tid]  = Vw[n0 + tid];
    }
    if (tid >= 128 && tid < 384) {
        cov_s[tid - 128] = cov[m0 + tid - 128];
        sc_s[tid - 128] = 0.f;
    }

    // ldmatrix per-thread invariants
    const uint32_t slane = lane & 7;
    const uint32_t ahi   = lane >> 4;           // A chunk bit
    const uint32_t bbit  = (lane >> 3) & 1;     // B chunk bit
    uint32_t arow_off[4], brow_off[2];
    #pragma unroll
    for (int mi = 0; mi < 4; mi++)
        arow_off[mi] = (uint32_t)((wm * 64 + mi * 16 + (lane & 15)) << 7);
    #pragma unroll
    for (int njp = 0; njp < 2; njp++)
        brow_off[njp] = (uint32_t)(((wn * 32 + njp * 16 + slane + (ahi << 3)) << 7)
                                   + STG_A);

    float acc[4][4][4] = {};

    // fragment loader for one kk (k = kk*16 halves)
    #define LOAD_FRAGS(ST_, KK_, AF_, BF_) do {                               \
        const uint32_t xa_ = ((((KK_) << 1) + ahi)  ^ slane) << 4;            \
        const uint32_t xb_ = ((((KK_) << 1) + bbit) ^ slane) << 4;            \
        _Pragma("unroll")                                                     \
        for (int mi_ = 0; mi_ < 4; mi_++)                                     \
            ldsm4(AF_[mi_], (ST_) + arow_off[mi_] + xa_);                     \
        _Pragma("unroll")                                                     \
        for (int nj_ = 0; nj_ < 2; nj_++)                                     \
            ldsm4(BF_[nj_], (ST_) + brow_off[nj_] + xb_);                     \
    } while (0)

    for (int s = 0; s < KSTAGES; s++) {
        // all warps finished reading buffer (s-1)%NST in the previous iter;
        // safe to overwrite it with stage s+3.
        __syncthreads();
        if (tid == 0 && s + 3 < KSTAGES) {
            const int p = (s + 3) % NST;
            mbar_expect_tx(mb + p * 8, STG);
            bulk_ld(sbase + p * STG,         Ablk + (size_t)(s + 3) * A_BLK_H, STG_A, mb + p * 8);
            bulk_ld(sbase + p * STG + STG_A, Bblk + (size_t)(s + 3) * B_BLK_H, STG - STG_A, mb + p * 8);
        }
        mbar_wait(mb + (s % NST) * 8, (uint32_t)((s >> 2) & 1));

        const uint32_t st = sbase + (s % NST) * STG;

        uint32_t af[2][4][4], bf[2][2][4];
        LOAD_FRAGS(st, 0, af[0], bf[0]);

        #pragma unroll
        for (int kk = 0; kk < 4; kk++) {
            const int cur = kk & 1, nxt = cur ^ 1;
            if (kk < 3) LOAD_FRAGS(st, kk + 1, af[nxt], bf[nxt]);
            #pragma unroll
            for (int mi = 0; mi < 4; mi++) {
                #pragma unroll
                for (int njp = 0; njp < 2; njp++) {
                    mma_f16(acc[mi][2*njp    ], af[cur][mi], &bf[cur][njp][0]);
                    mma_f16(acc[mi][2*njp + 1], af[cur][mi], &bf[cur][njp][2]);
                }
            }
        }
    }

    // Epilogue: tanh + dot with V, reduce per token row.
    // acc[mi][nj]: n base = wn*32 + nj*8; elems: [0]=(r,2c) [1]=(r,2c+1)
    // [2]=(r+8,2c) [3]=(r+8,2c+1)
    #pragma unroll
    for (int mi = 0; mi < 4; mi++) {
        const int mr = wm * 64 + mi * 16 + r;
        const float cv0 = cov_s[mr], cv1 = cov_s[mr + 8];
        float s0 = 0.f, s1 = 0.f;
        #pragma unroll
        for (int nj = 0; nj < 4; nj++) {
            #pragma unroll
            for (int e = 0; e < 2; e++) {
                const int u = wn * 32 + nj * 8 + 2 * c + e;
                const float hb = hb_s[u], wc = wc_s[u], vv = v_s[u];
                s0 += vv * fast_tanh(acc[mi][nj][e]     + hb + cv0 * wc);
                s1 += vv * fast_tanh(acc[mi][nj][e + 2] + hb + cv1 * wc);
            }
        }
        s0 += __shfl_xor_sync(0xffffffffu, s0, 1);
        s0 += __shfl_xor_sync(0xffffffffu, s0, 2);
        s1 += __shfl_xor_sync(0xffffffffu, s1, 1);
        s1 += __shfl_xor_sync(0xffffffffu, s1, 2);
        if (c == 0) {
            atomicAdd(&sc_s[mr],     s0);
            atomicAdd(&sc_s[mr + 8], s1);
        }
    }
    __syncthreads();
    if (tid < 256) atomicAdd(&g_score[m0 + tid], sc_s[tid]);
}

// ---------------------------------------------------------------------------
// Kernel C1: softmax over S per batch; write attn + coverage; zero ctx region.
// ---------------------------------------------------------------------------
__global__ void softmax_cov_kernel(const float* __restrict__ prev_cov,
                                   float* __restrict__ out) {
    __shared__ float red[256];
    const int b = blockIdx.x, tid = threadIdx.x;
    const int base = b * SS;

    float l[8];
    float mx = -1e30f;
    #pragma unroll
    for (int i = 0; i < 8; i++) {
        l[i] = g_score[base + i * 256 + tid];
        mx = fmaxf(mx, l[i]);
    }
    red[tid] = mx; __syncthreads();
    for (int o = 128; o > 0; o >>= 1) {
        if (tid < o) red[tid] = fmaxf(red[tid], red[tid + o]);
        __syncthreads();
    }
    const float gmax = red[0];
    __syncthreads();

    float s = 0.f;
    #pragma unroll
    for (int i = 0; i < 8; i++) { l[i] = expf(l[i] - gmax); s += l[i]; }
    red[tid] = s; __syncthreads();
    for (int o = 128; o > 0; o >>= 1) {
        if (tid < o) red[tid] += red[tid + o];
        __syncthreads();
    }
    const float inv = 1.f / red[0];

    #pragma unroll
    for (int i = 0; i < 8; i++) {
        const int idx = base + i * 256 + tid;
        const float w = l[i] * inv;
        out[ATTN_OFF + idx] = w;
        out[COV_OFF + idx]  = w + prev_cov[idx];
    }
    for (int i = tid; i < DD; i += 256) out[CTX_OFF + b * DD + i] = 0.f;
}

// ---------------------------------------------------------------------------
// Kernel C2: context[b,d] = sum_s attn[b,s] * X[b,s,d], reading blocked g_Xh.
// Block row addressing: token m -> (mt=m>>8, row=m&255), chunk (kt, ch).
// Each thread owns 8 d-values (one 16B chunk column) to keep LDG.128s.
// grid (128 chunk-cols... ) -> use (DD/8 / 64 = 2, B, SSPLIT=8), 256 thr? 
// Simpler: thread owns one (kt,ch) pair per 8 d; loop s over 256 tokens.
// ---------------------------------------------------------------------------
__global__ void context_kernel(float* __restrict__ out) {
    __shared__ float aw[256];
    const int tid = threadIdx.x;
    const int chunk = blockIdx.x * 128 + (tid >> 1);   // 0..127: (kt,ch) pair
    const int half8 = tid & 1;                          // which 4 of 8 halves? no:
    // Each (kt,ch) chunk = 8 halves; 2 threads split it -> 4 halves each.
    const int kt = chunk >> 3, ch = chunk & 7;
    const int b = blockIdx.y;
    const int sbeg = blockIdx.z * 256;

    aw[tid] = out[ATTN_OFF + b * SS + sbeg + tid];
    __syncthreads();

    float a0 = 0.f, a1 = 0.f, a2 = 0.f, a3 = 0.f;
    for (int s = 0; s < 256; s++) {
        const int m = b * SS + sbeg + s;
        const int mt = m >> 8, row = m & 255;
        const char* blk = (const char*)(g_Xh + ((size_t)mt * KSTAGES + kt) * A_BLK_H);
        const __half2* p = (const __half2*)(blk + (row << 7)
                           + ((ch ^ (row & 7)) << 4) + half8 * 8);
        const float w = aw[s];
        float2 f0 = __half22float2(p[0]);
        float2 f1 = __half22float2(p[1]);
        a0 += w * f0.x; a1 += w * f0.y; a2 += w * f1.x; a3 += w * f1.y;
    }
    const int d = kt * 64 + ch * 8 + half8 * 4;
    atomicAdd(&out[CTX_OFF + b * DD + d    ], a0);
    atomicAdd(&out[CTX_OFF + b * DD + d + 1], a1);
    atomicAdd(&out[CTX_OFF + b * DD + d + 2], a2);
    atomicAdd(&out[CTX_OFF + b * DD + d + 3], a3);
}

// ---------------------------------------------------------------------------
extern "C" void kernel_launch(void* const* d_in, const int* in_sizes, int n_in,
                              void* d_out, int out_size) {
    int base = 3;
    if (n_in > 4 && in_sizes[3] != BS) base = 4;  // skip use_coverage scalar if present

    const float* dec      = (const float*)d_in[0];
    const float* enc      = (const float*)d_in[1];
    const float* prev_cov = (const float*)d_in[base + 0];
    const float* Ws_w     = (const float*)d_in[base + 1];
    const float* Ws_b     = (const float*)d_in[base + 2];
    const float* Wh_w     = (const float*)d_in[base + 3];
    const float* Wh_b     = (const float*)d_in[base + 4];
    const float* Wc_w     = (const float*)d_in[base + 5];
    const float* Wc_b     = (const float*)d_in[base + 6];
    const float* V_w      = (const float*)d_in[base + 7];
    // V_b unused: softmax is shift-invariant.

    float* out = (float*)d_out;

    cudaFuncSetAttribute(score_gemm_fp16,
                         cudaFuncAttributeMaxDynamicSharedMemorySize, SMEM_NEED);

    convert_x_kernel<<<16384, 512>>>(enc);
    transpose_w_kernel<<<dim3(UU / 32, DD / 32), dim3(32, 8)>>>(Ws_w);
    hbias_kernel<<<dim3(UU / 256, BB), 256>>>(dec, Wh_w, Wh_b, Ws_b, Wc_b);
    score_gemm_fp16<<<dim3(UU / BN, BS / BM), 512, SMEM_NEED>>>(Wc_w, V_w, prev_cov);
    softmax_cov_kernel<<<BB, 256>>>(prev_cov, out);
    context_kernel<<<dim3(1, BB, 8), 256>>>(out);
    (void)out_size;
}

// round 8
// speedup vs baseline: 2.2465x; 1.0181x over previous
#include <cuda_runtime.h>
#include <cuda_fp16.h>
#include <cstdint>

// Problem constants
#define BB 32
#define SS 2048
#define DD 1024
#define UU 1024
#define BS (BB*SS)            // 65536 tokens

// Output layout: context [B,D] | attn [B,S] | coverage [B,S]
#define CTX_OFF 0
#define ATTN_OFF (BB*DD)
#define COV_OFF  (BB*DD + BB*SS)

// GEMM tiling
#define BM 256
#define BN 128
#define BKH 64                         // K-chunk in halves (128B rows)
#define KSTAGES 16                     // DD / BKH
#define A_BLK_H 16384                  // halves per A tile block (256*64) = 32KB
#define B_BLK_H 8192                   // halves per B tile block (128*64) = 16KB

// Device scratch (allocation-free rule: __device__ globals)
__device__ float  g_hbias[BB*UU];          // dec@Wh + Wh_b + Ws_b + Wc_b
__device__ float  g_score[BS];             // pre-softmax scores
__device__ __half g_Xh[(size_t)BS*DD];     // enc_output fp16, tile-blocked+swizzled
__device__ __half g_Wth[UU*DD];            // Ws_w^T fp16, tile-blocked+swizzled

// ---------------------------------------------------------------------------
// helpers
// ---------------------------------------------------------------------------
__device__ __forceinline__ uint32_t smem_u32(const void* p) {
    uint32_t a;
    asm("{ .reg .u64 t; cvta.to.shared.u64 t, %1; cvt.u32.u64 %0, t; }"
        : "=r"(a) : "l"(p));
    return a;
}

__device__ __forceinline__ void mbar_init(uint32_t addr, uint32_t cnt) {
    asm volatile("mbarrier.init.shared.b64 [%0], %1;" :: "r"(addr), "r"(cnt) : "memory");
}

__device__ __forceinline__ void mbar_expect_tx(uint32_t addr, uint32_t bytes) {
    asm volatile("mbarrier.arrive.expect_tx.shared.b64 _, [%0], %1;"
                 :: "r"(addr), "r"(bytes) : "memory");
}

__device__ __forceinline__ void mbar_wait(uint32_t addr, uint32_t parity) {
    asm volatile(
        "{\n\t.reg .pred P;\n"
        "WAIT_%=: \n\t"
        "mbarrier.try_wait.parity.acquire.cta.shared::cta.b64 P, [%0], %1, 0x989680;\n\t"
        "@P bra DONE_%=;\n\t"
        "bra WAIT_%=;\n"
        "DONE_%=: \n\t}"
        :: "r"(addr), "r"(parity) : "memory");
}

__device__ __forceinline__ void bulk_ld(uint32_t sdst, const void* gsrc,
                                        uint32_t bytes, uint32_t mbar) {
    asm volatile(
        "cp.async.bulk.shared::cta.global.mbarrier::complete_tx::bytes "
        "[%0], [%1], %2, [%3];"
        :: "r"(sdst), "l"(gsrc), "r"(bytes), "r"(mbar) : "memory");
}

__device__ __forceinline__ void fence_proxy_async_cta() {
    asm volatile("fence.proxy.async.shared::cta;" ::: "memory");
}

__device__ __forceinline__ void ldsm4(uint32_t* r, uint32_t addr) {
    asm volatile("ldmatrix.sync.aligned.m8n8.x4.shared.b16 {%0,%1,%2,%3}, [%4];"
                 : "=r"(r[0]), "=r"(r[1]), "=r"(r[2]), "=r"(r[3]) : "r"(addr));
}

__device__ __forceinline__ void mma_f16(float* d, const uint32_t* a, const uint32_t* b) {
    asm volatile(
        "mma.sync.aligned.m16n8k16.row.col.f32.f16.f16.f32 "
        "{%0,%1,%2,%3}, {%4,%5,%6,%7}, {%8,%9}, {%0,%1,%2,%3};\n"
        : "+f"(d[0]), "+f"(d[1]), "+f"(d[2]), "+f"(d[3])
        : "r"(a[0]), "r"(a[1]), "r"(a[2]), "r"(a[3]),
          "r"(b[0]), "r"(b[1]));
}

__device__ __forceinline__ float fast_tanh(float x) {
    float t;
    asm("tanh.approx.f32 %0, %1;" : "=f"(t) : "f"(x));
    return t;
}

// ---------------------------------------------------------------------------
// Kernel X: convert enc fp32 -> fp16 into tile-blocked swizzled layout.
// Block (mt, kt): 256 rows x 64 halves (32KB contiguous), 128B rows with
// 16B-chunk XOR swizzle: off = (row<<7) + ((ch ^ (row&7))<<4).
// ---------------------------------------------------------------------------
__global__ void convert_x_kernel(const float* __restrict__ X) {
    const size_t i = (size_t)blockIdx.x * 512 + threadIdx.x;  // 8.39M chunks
    const int m  = (int)(i >> 7);       // token row
    const int cg = (int)(i & 127);      // chunk-in-row
    const int kt = cg >> 3;
    const int ch = cg & 7;
    const int mt = m >> 8;
    const int row = m & 255;

    const float4* src = (const float4*)(X + (size_t)m * DD + kt * 64 + ch * 8);
    const float4 f0 = src[0];
    const float4 f1 = src[1];
    __half2 h0 = __float22half2_rn(make_float2(f0.x, f0.y));
    __half2 h1 = __float22half2_rn(make_float2(f0.z, f0.w));
    __half2 h2 = __float22half2_rn(make_float2(f1.x, f1.y));
    __half2 h3 = __float22half2_rn(make_float2(f1.z, f1.w));
    uint4 o;
    o.x = *(uint32_t*)&h0; o.y = *(uint32_t*)&h1;
    o.z = *(uint32_t*)&h2; o.w = *(uint32_t*)&h3;

    char* blk = (char*)(g_Xh + ((size_t)mt * KSTAGES + kt) * A_BLK_H);
    *(uint4*)(blk + (row << 7) + ((ch ^ (row & 7)) << 4)) = o;
}

// ---------------------------------------------------------------------------
// Kernel T: transpose + convert Ws_w [D,U] fp32 -> g_Wth tile-blocked swizzled.
// ---------------------------------------------------------------------------
__global__ void transpose_w_kernel(const float* __restrict__ W) {
    __shared__ float t[32][33];
    const int bx = blockIdx.x * 32;   // u base
    const int by = blockIdx.y * 32;   // d base
    #pragma unroll
    for (int j = 0; j < 4; j++)
        t[threadIdx.y + j * 8][threadIdx.x] =
            W[(size_t)(by + threadIdx.y + j * 8) * UU + bx + threadIdx.x];
    __syncthreads();
    #pragma unroll
    for (int j = 0; j < 4; j++) {
        const int u = bx + threadIdx.y + j * 8;
        const int d = by + threadIdx.x;
        const int nt = u >> 7, rowB = u & 127;
        const int kt = d >> 6, ch = (d & 63) >> 3, pos = d & 7;
        char* blk = (char*)(g_Wth + ((size_t)nt * KSTAGES + kt) * B_BLK_H);
        *(__half*)(blk + (rowB << 7) + ((ch ^ (rowB & 7)) << 4) + pos * 2) =
            __float2half(t[threadIdx.x][threadIdx.y + j * 8]);
    }
}

// ---------------------------------------------------------------------------
// Kernel A: hbias[b][u] = dec[b,:]@Wh_w[:,u] + Wh_b[u] + Ws_b[u] + Wc_b[u]
// ---------------------------------------------------------------------------
__global__ void hbias_kernel(const float* __restrict__ dec,
                             const float* __restrict__ Whw,
                             const float* __restrict__ Whb,
                             const float* __restrict__ Wsb,
                             const float* __restrict__ Wcb) {
    __shared__ float dh[DD];
    const int b = blockIdx.y;
    const int u = blockIdx.x * 256 + threadIdx.x;
    for (int i = threadIdx.x; i < DD; i += 256) dh[i] = dec[b*DD + i];
    __syncthreads();

    float a0 = 0.f, a1 = 0.f, a2 = 0.f, a3 = 0.f;
    #pragma unroll 4
    for (int d = 0; d < DD; d += 4) {
        a0 += dh[d+0] * Whw[(size_t)(d+0)*UU + u];
        a1 += dh[d+1] * Whw[(size_t)(d+1)*UU + u];
        a2 += dh[d+2] * Whw[(size_t)(d+2)*UU + u];
        a3 += dh[d+3] * Whw[(size_t)(d+3)*UU + u];
    }
    g_hbias[b*UU + u] = (a0 + a1) + (a2 + a3) + Whb[u] + Wsb[u] + Wcb[u];

    int gid = (blockIdx.y * 4 + blockIdx.x) * 256 + threadIdx.x;
    g_score[gid] = 0.f;
    g_score[gid + 32768] = 0.f;
}

// ---------------------------------------------------------------------------
// Kernel B: fp16 mma.sync fused score GEMM, cp.async.bulk + mbarrier pipeline.
// BM=256, BN=128, BKH=64. 512 threads = 16 warps (4m x 4n), warp 64x32.
// ---------------------------------------------------------------------------
#define NST 4
#define STG 49152                      // 32KB A + 16KB B
#define STG_A 32768
#define OFF_HB   (NST*STG)             // 196608
#define OFF_WC   (OFF_HB + 512)
#define OFF_V    (OFF_WC + 512)
#define OFF_COV  (OFF_V + 512)
#define OFF_SC   (OFF_COV + 1024)
#define OFF_MBAR (OFF_SC + 1024)       // 4 mbarriers
#define SMEM_NEED (OFF_MBAR + 64)      // 200256

__global__ void __launch_bounds__(512, 1)
score_gemm_fp16(const float* __restrict__ Wcw,
                const float* __restrict__ Vw,
                const float* __restrict__ cov) {
    extern __shared__ char sm[];
    const int tid  = threadIdx.x;
    const int lane = tid & 31;
    const int wid  = tid >> 5;
    const int wm   = wid >> 2;        // 0..3
    const int wn   = wid & 3;         // 0..3
    const int r    = lane >> 2;       // 0..7
    const int c    = lane & 3;        // 0..3

    const int n0 = blockIdx.x * BN;
    const int m0 = blockIdx.y * BM;
    const int b  = m0 >> 11;

    float* hb_s  = (float*)(sm + OFF_HB);    // [128]
    float* wc_s  = (float*)(sm + OFF_WC);    // [128]
    float* v_s   = (float*)(sm + OFF_V);     // [128]
    float* cov_s = (float*)(sm + OFF_COV);   // [256]
    float* sc_s  = (float*)(sm + OFF_SC);    // [256]

    const uint32_t sbase = smem_u32(sm);
    const uint32_t mb    = sbase + OFF_MBAR;

    if (tid == 0) {
        #pragma unroll
        for (int p = 0; p < NST; p++) mbar_init(mb + p * 8, 1);
    }
    __syncthreads();
    fence_proxy_async_cta();

    const __half* Ablk = g_Xh  + (size_t)blockIdx.y * KSTAGES * A_BLK_H;
    const __half* Bblk = g_Wth + (size_t)blockIdx.x * KSTAGES * B_BLK_H;

    // prologue: issue stages 0..2
    if (tid == 0) {
        #pragma unroll
        for (int p = 0; p < 3; p++) {
            mbar_expect_tx(mb + p * 8, STG);
            bulk_ld(sbase + p * STG,         Ablk + (size_t)p * A_BLK_H, STG_A, mb + p * 8);
            bulk_ld(sbase + p * STG + STG_A, Bblk + (size_t)p * B_BLK_H, STG - STG_A, mb + p * 8);
        }
    }

    if (tid < 128) {
        hb_s[tid] = g_hbias[b * UU + n0 + tid];
        wc_s[tid] = Wcw[n0 + tid];
        v_s[tid]  = Vw[n0 + tid];
    }
    if (tid >= 128 && tid < 384) {
        cov_s[tid - 128] = cov[m0 + tid - 128];
        sc_s[tid - 128] = 0.f;
    }

    // ldmatrix per-thread invariants
    const uint32_t slane = lane & 7;
    const uint32_t ahi   = lane >> 4;           // A chunk bit
    const uint32_t bbit  = (lane >> 3) & 1;     // B chunk bit
    uint32_t arow_off[4], brow_off[2];
    #pragma unroll
    for (int mi = 0; mi < 4; mi++)
        arow_off[mi] = (uint32_t)((wm * 64 + mi * 16 + (lane & 15)) << 7);
    #pragma unroll
    for (int njp = 0; njp < 2; njp++)
        brow_off[njp] = (uint32_t)(((wn * 32 + njp * 16 + slane + (ahi << 3)) << 7)
                                   + STG_A);

    float acc[4][4][4] = {};

    #define LOAD_FRAGS(ST_, KK_, AF_, BF_) do {                               \
        const uint32_t xa_ = ((((KK_) << 1) + ahi)  ^ slane) << 4;            \
        const uint32_t xb_ = ((((KK_) << 1) + bbit) ^ slane) << 4;            \
        _Pragma("unroll")                                                     \
        for (int mi_ = 0; mi_ < 4; mi_++)                                     \
            ldsm4(AF_[mi_], (ST_) + arow_off[mi_] + xa_);                     \
        _Pragma("unroll")                                                     \
        for (int nj_ = 0; nj_ < 2; nj_++)                                     \
            ldsm4(BF_[nj_], (ST_) + brow_off[nj_] + xb_);                     \
    } while (0)

    for (int s = 0; s < KSTAGES; s++) {
        __syncthreads();
        if (tid == 0 && s + 3 < KSTAGES) {
            const int p = (s + 3) % NST;
            mbar_expect_tx(mb + p * 8, STG);
            bulk_ld(sbase + p * STG,         Ablk + (size_t)(s + 3) * A_BLK_H, STG_A, mb + p * 8);
            bulk_ld(sbase + p * STG + STG_A, Bblk + (size_t)(s + 3) * B_BLK_H, STG - STG_A, mb + p * 8);
        }
        mbar_wait(mb + (s % NST) * 8, (uint32_t)((s >> 2) & 1));

        const uint32_t st = sbase + (s % NST) * STG;

        uint32_t af[2][4][4], bf[2][2][4];
        LOAD_FRAGS(st, 0, af[0], bf[0]);

        #pragma unroll
        for (int kk = 0; kk < 4; kk++) {
            const int cur = kk & 1, nxt = cur ^ 1;
            if (kk < 3) LOAD_FRAGS(st, kk + 1, af[nxt], bf[nxt]);
            #pragma unroll
            for (int mi = 0; mi < 4; mi++) {
                #pragma unroll
                for (int njp = 0; njp < 2; njp++) {
                    mma_f16(acc[mi][2*njp    ], af[cur][mi], &bf[cur][njp][0]);
                    mma_f16(acc[mi][2*njp + 1], af[cur][mi], &bf[cur][njp][2]);
                }
            }
        }
    }

    // Epilogue: tanh + dot with V, reduce per token row.
    #pragma unroll
    for (int mi = 0; mi < 4; mi++) {
        const int mr = wm * 64 + mi * 16 + r;
        const float cv0 = cov_s[mr], cv1 = cov_s[mr + 8];
        float s0 = 0.f, s1 = 0.f;
        #pragma unroll
        for (int nj = 0; nj < 4; nj++) {
            #pragma unroll
            for (int e = 0; e < 2; e++) {
                const int u = wn * 32 + nj * 8 + 2 * c + e;
                const float hb = hb_s[u], wc = wc_s[u], vv = v_s[u];
                s0 += vv * fast_tanh(acc[mi][nj][e]     + hb + cv0 * wc);
                s1 += vv * fast_tanh(acc[mi][nj][e + 2] + hb + cv1 * wc);
            }
        }
        s0 += __shfl_xor_sync(0xffffffffu, s0, 1);
        s0 += __shfl_xor_sync(0xffffffffu, s0, 2);
        s1 += __shfl_xor_sync(0xffffffffu, s1, 1);
        s1 += __shfl_xor_sync(0xffffffffu, s1, 2);
        if (c == 0) {
            atomicAdd(&sc_s[mr],     s0);
            atomicAdd(&sc_s[mr + 8], s1);
        }
    }
    __syncthreads();
    if (tid < 256) atomicAdd(&g_score[m0 + tid], sc_s[tid]);
}

// ---------------------------------------------------------------------------
// Kernel C1: softmax over S per batch; write attn + coverage; zero ctx region.
// ---------------------------------------------------------------------------
__global__ void softmax_cov_kernel(const float* __restrict__ prev_cov,
                                   float* __restrict__ out) {
    __shared__ float red[256];
    const int b = blockIdx.x, tid = threadIdx.x;
    const int base = b * SS;

    float l[8];
    float mx = -1e30f;
    #pragma unroll
    for (int i = 0; i < 8; i++) {
        l[i] = g_score[base + i * 256 + tid];
        mx = fmaxf(mx, l[i]);
    }
    red[tid] = mx; __syncthreads();
    for (int o = 128; o > 0; o >>= 1) {
        if (tid < o) red[tid] = fmaxf(red[tid], red[tid + o]);
        __syncthreads();
    }
    const float gmax = red[0];
    __syncthreads();

    float s = 0.f;
    #pragma unroll
    for (int i = 0; i < 8; i++) { l[i] = expf(l[i] - gmax); s += l[i]; }
    red[tid] = s; __syncthreads();
    for (int o = 128; o > 0; o >>= 1) {
        if (tid < o) red[tid] += red[tid + o];
        __syncthreads();
    }
    const float inv = 1.f / red[0];

    #pragma unroll
    for (int i = 0; i < 8; i++) {
        const int idx = base + i * 256 + tid;
        const float w = l[i] * inv;
        out[ATTN_OFF + idx] = w;
        out[COV_OFF + idx]  = w + prev_cov[idx];
    }
    for (int i = tid; i < DD; i += 256) out[CTX_OFF + b * DD + i] = 0.f;
}

// ---------------------------------------------------------------------------
// Kernel C2: context[b,d] = sum_s attn[b,s] * X[b,s,d], blocked g_Xh.
// One thread per 16B chunk (8 d-values); 128 threads; grid (B=32, SSPLIT=16).
// ---------------------------------------------------------------------------
__global__ void context_kernel(float* __restrict__ out) {
    __shared__ float aw[128];
    const int tid = threadIdx.x;          // 0..127 = (kt,ch)
    const int b = blockIdx.x;
    const int sbeg = blockIdx.y * 128;

    aw[tid] = out[ATTN_OFF + b * SS + sbeg + tid];
    __syncthreads();

    const int kt = tid >> 3, ch = tid & 7;
    const int mbase = b * SS + sbeg;
    float acc[8] = {};

    #pragma unroll 4
    for (int s = 0; s < 128; s++) {
        const int m = mbase + s;
        const int mt = m >> 8, row = m & 255;
        const char* blk = (const char*)(g_Xh + ((size_t)mt * KSTAGES + kt) * A_BLK_H);
        const uint4 v = *(const uint4*)(blk + (row << 7) + ((ch ^ (row & 7)) << 4));
        const __half2* h = (const __half2*)&v;
        const float w = aw[s];
        #pragma unroll
        for (int j = 0; j < 4; j++) {
            const float2 f = __half22float2(h[j]);
            acc[2*j]   += w * f.x;
            acc[2*j+1] += w * f.y;
        }
    }
    const int d = kt * 64 + ch * 8;
    #pragma unroll
    for (int j = 0; j < 8; j++)
        atomicAdd(&out[CTX_OFF + b * DD + d + j], acc[j]);
}

// ---------------------------------------------------------------------------
extern "C" void kernel_launch(void* const* d_in, const int* in_sizes, int n_in,
                              void* d_out, int out_size) {
    int base = 3;
    if (n_in > 4 && in_sizes[3] != BS) base = 4;  // skip use_coverage scalar if present

    const float* dec      = (const float*)d_in[0];
    const float* enc      = (const float*)d_in[1];
    const float* prev_cov = (const float*)d_in[base + 0];
    const float* Ws_w     = (const float*)d_in[base + 1];
    const float* Ws_b     = (const float*)d_in[base + 2];
    const float* Wh_w     = (const float*)d_in[base + 3];
    const float* Wh_b     = (const float*)d_in[base + 4];
    const float* Wc_w     = (const float*)d_in[base + 5];
    const float* Wc_b     = (const float*)d_in[base + 6];
    const float* V_w      = (const float*)d_in[base + 7];
    // V_b unused: softmax is shift-invariant.

    float* out = (float*)d_out;

    cudaFuncSetAttribute(score_gemm_fp16,
                         cudaFuncAttributeMaxDynamicSharedMemorySize, SMEM_NEED);

    convert_x_kernel<<<16384, 512>>>(enc);
    transpose_w_kernel<<<dim3(UU / 32, DD / 32), dim3(32, 8)>>>(Ws_w);
    hbias_kernel<<<dim3(UU / 256, BB), 256>>>(dec, Wh_w, Wh_b, Ws_b, Wc_b);
    score_gemm_fp16<<<dim3(UU / BN, BS / BM), 512, SMEM_NEED>>>(Wc_w, V_w, prev_cov);
    softmax_cov_kernel<<<BB, 256>>>(prev_cov, out);
    context_kernel<<<dim3(BB, 16), 128>>>(out);
    (void)out_size;
}

// round 9
// speedup vs baseline: 2.3723x; 1.0560x over previous
#include <cuda_runtime.h>
#include <cuda_fp16.h>
#include <cstdint>

// Problem constants
#define BB 32
#define SS 2048
#define DD 1024
#define UU 1024
#define BS (BB*SS)            // 65536 tokens

// Output layout: context [B,D] | attn [B,S] | coverage [B,S]
#define CTX_OFF 0
#define ATTN_OFF (BB*DD)
#define COV_OFF  (BB*DD + BB*SS)

// GEMM tiling
#define BM 256
#define BN 128
#define BKH 64                         // K-chunk in halves (128B rows)
#define KSTAGES 16                     // DD / BKH
#define A_BLK_H 16384                  // halves per A tile block (256*64) = 32KB
#define B_BLK_H 8192                   // halves per B tile block (128*64) = 16KB

// Device scratch (allocation-free rule: __device__ globals)
__device__ float  g_hbias[BB*UU];          // dec@Wh + Wh_b + Ws_b + Wc_b
__device__ float  g_score[BS];             // pre-softmax scores
__device__ __half g_Xh[(size_t)BS*DD];     // enc_output fp16, tile-blocked+swizzled
__device__ __half g_Wth[UU*DD];            // Ws_w^T fp16, tile-blocked+swizzled

// ---------------------------------------------------------------------------
// helpers
// ---------------------------------------------------------------------------
__device__ __forceinline__ uint32_t smem_u32(const void* p) {
    uint32_t a;
    asm("{ .reg .u64 t; cvta.to.shared.u64 t, %1; cvt.u32.u64 %0, t; }"
        : "=r"(a) : "l"(p));
    return a;
}

__device__ __forceinline__ void mbar_init(uint32_t addr, uint32_t cnt) {
    asm volatile("mbarrier.init.shared.b64 [%0], %1;" :: "r"(addr), "r"(cnt) : "memory");
}

__device__ __forceinline__ void mbar_expect_tx(uint32_t addr, uint32_t bytes) {
    asm volatile("mbarrier.arrive.expect_tx.shared.b64 _, [%0], %1;"
                 :: "r"(addr), "r"(bytes) : "memory");
}

__device__ __forceinline__ void mbar_arrive(uint32_t addr) {
    asm volatile("mbarrier.arrive.shared.b64 _, [%0];" :: "r"(addr) : "memory");
}

__device__ __forceinline__ void mbar_wait(uint32_t addr, uint32_t parity) {
    asm volatile(
        "{\n\t.reg .pred P;\n"
        "WAIT_%=: \n\t"
        "mbarrier.try_wait.parity.acquire.cta.shared::cta.b64 P, [%0], %1, 0x989680;\n\t"
        "@P bra DONE_%=;\n\t"
        "bra WAIT_%=;\n"
        "DONE_%=: \n\t}"
        :: "r"(addr), "r"(parity) : "memory");
}

__device__ __forceinline__ void bulk_ld(uint32_t sdst, const void* gsrc,
                                        uint32_t bytes, uint32_t mbar) {
    asm volatile(
        "cp.async.bulk.shared::cta.global.mbarrier::complete_tx::bytes "
        "[%0], [%1], %2, [%3];"
        :: "r"(sdst), "l"(gsrc), "r"(bytes), "r"(mbar) : "memory");
}

__device__ __forceinline__ void fence_proxy_async_cta() {
    asm volatile("fence.proxy.async.shared::cta;" ::: "memory");
}

__device__ __forceinline__ void ldsm4(uint32_t* r, uint32_t addr) {
    asm volatile("ldmatrix.sync.aligned.m8n8.x4.shared.b16 {%0,%1,%2,%3}, [%4];"
                 : "=r"(r[0]), "=r"(r[1]), "=r"(r[2]), "=r"(r[3]) : "r"(addr));
}

__device__ __forceinline__ void mma_f16(float* d, const uint32_t* a, const uint32_t* b) {
    asm volatile(
        "mma.sync.aligned.m16n8k16.row.col.f32.f16.f16.f32 "
        "{%0,%1,%2,%3}, {%4,%5,%6,%7}, {%8,%9}, {%0,%1,%2,%3};\n"
        : "+f"(d[0]), "+f"(d[1]), "+f"(d[2]), "+f"(d[3])
        : "r"(a[0]), "r"(a[1]), "r"(a[2]), "r"(a[3]),
          "r"(b[0]), "r"(b[1]));
}

__device__ __forceinline__ float fast_tanh(float x) {
    float t;
    asm("tanh.approx.f32 %0, %1;" : "=f"(t) : "f"(x));
    return t;
}

// ---------------------------------------------------------------------------
// Kernel X: convert enc fp32 -> fp16 into tile-blocked swizzled layout.
// ---------------------------------------------------------------------------
__global__ void convert_x_kernel(const float* __restrict__ X) {
    const size_t i = (size_t)blockIdx.x * 512 + threadIdx.x;  // 8.39M chunks
    const int m  = (int)(i >> 7);       // token row
    const int cg = (int)(i & 127);      // chunk-in-row
    const int kt = cg >> 3;
    const int ch = cg & 7;
    const int mt = m >> 8;
    const int row = m & 255;

    const float4* src = (const float4*)(X + (size_t)m * DD + kt * 64 + ch * 8);
    const float4 f0 = src[0];
    const float4 f1 = src[1];
    __half2 h0 = __float22half2_rn(make_float2(f0.x, f0.y));
    __half2 h1 = __float22half2_rn(make_float2(f0.z, f0.w));
    __half2 h2 = __float22half2_rn(make_float2(f1.x, f1.y));
    __half2 h3 = __float22half2_rn(make_float2(f1.z, f1.w));
    uint4 o;
    o.x = *(uint32_t*)&h0; o.y = *(uint32_t*)&h1;
    o.z = *(uint32_t*)&h2; o.w = *(uint32_t*)&h3;

    char* blk = (char*)(g_Xh + ((size_t)mt * KSTAGES + kt) * A_BLK_H);
    *(uint4*)(blk + (row << 7) + ((ch ^ (row & 7)) << 4)) = o;
}

// ---------------------------------------------------------------------------
// Kernel T: transpose + convert Ws_w [D,U] fp32 -> g_Wth tile-blocked swizzled.
// ---------------------------------------------------------------------------
__global__ void transpose_w_kernel(const float* __restrict__ W) {
    __shared__ float t[32][33];
    const int bx = blockIdx.x * 32;   // u base
    const int by = blockIdx.y * 32;   // d base
    #pragma unroll
    for (int j = 0; j < 4; j++)
        t[threadIdx.y + j * 8][threadIdx.x] =
            W[(size_t)(by + threadIdx.y + j * 8) * UU + bx + threadIdx.x];
    __syncthreads();
    #pragma unroll
    for (int j = 0; j < 4; j++) {
        const int u = bx + threadIdx.y + j * 8;
        const int d = by + threadIdx.x;
        const int nt = u >> 7, rowB = u & 127;
        const int kt = d >> 6, ch = (d & 63) >> 3, pos = d & 7;
        char* blk = (char*)(g_Wth + ((size_t)nt * KSTAGES + kt) * B_BLK_H);
        *(__half*)(blk + (rowB << 7) + ((ch ^ (rowB & 7)) << 4) + pos * 2) =
            __float2half(t[threadIdx.x][threadIdx.y + j * 8]);
    }
}

// ---------------------------------------------------------------------------
// Kernel A: hbias[b][u] = dec[b,:]@Wh_w[:,u] + Wh_b[u] + Ws_b[u] + Wc_b[u]
// ---------------------------------------------------------------------------
__global__ void hbias_kernel(const float* __restrict__ dec,
                             const float* __restrict__ Whw,
                             const float* __restrict__ Whb,
                             const float* __restrict__ Wsb,
                             const float* __restrict__ Wcb) {
    __shared__ float dh[DD];
    const int b = blockIdx.y;
    const int u = blockIdx.x * 256 + threadIdx.x;
    for (int i = threadIdx.x; i < DD; i += 256) dh[i] = dec[b*DD + i];
    __syncthreads();

    float a0 = 0.f, a1 = 0.f, a2 = 0.f, a3 = 0.f;
    #pragma unroll 4
    for (int d = 0; d < DD; d += 4) {
        a0 += dh[d+0] * Whw[(size_t)(d+0)*UU + u];
        a1 += dh[d+1] * Whw[(size_t)(d+1)*UU + u];
        a2 += dh[d+2] * Whw[(size_t)(d+2)*UU + u];
        a3 += dh[d+3] * Whw[(size_t)(d+3)*UU + u];
    }
    g_hbias[b*UU + u] = (a0 + a1) + (a2 + a3) + Whb[u] + Wsb[u] + Wcb[u];

    int gid = (blockIdx.y * 4 + blockIdx.x) * 256 + threadIdx.x;
    g_score[gid] = 0.f;
    g_score[gid + 32768] = 0.f;
}

// ---------------------------------------------------------------------------
// Kernel B: fp16 mma.sync fused score GEMM, bulk-copy pipeline with
// producer/consumer mbarriers (NO per-stage __syncthreads -> warps skew,
// LDSM bursts overlap other warps' HMMA).
// BM=256, BN=128, BKH=64. 512 threads = 16 warps (4m x 4n), warp 64x32.
// ---------------------------------------------------------------------------
#define NST 4
#define STG 49152                      // 32KB A + 16KB B
#define STG_A 32768
#define OFF_HB    (NST*STG)            // 196608
#define OFF_WC    (OFF_HB + 512)
#define OFF_V     (OFF_WC + 512)
#define OFF_COV   (OFF_V + 512)
#define OFF_SC    (OFF_COV + 1024)
#define OFF_MBAR  (OFF_SC + 1024)      // 4 full mbarriers
#define OFF_MBARE (OFF_MBAR + 32)      // 4 empty mbarriers
#define SMEM_NEED (OFF_MBARE + 32)     // 200256

__global__ void __launch_bounds__(512, 1)
score_gemm_fp16(const float* __restrict__ Wcw,
                const float* __restrict__ Vw,
                const float* __restrict__ cov) {
    extern __shared__ char sm[];
    const int tid  = threadIdx.x;
    const int lane = tid & 31;
    const int wid  = tid >> 5;
    const int wm   = wid >> 2;        // 0..3
    const int wn   = wid & 3;         // 0..3
    const int r    = lane >> 2;       // 0..7
    const int c    = lane & 3;        // 0..3

    const int n0 = blockIdx.x * BN;
    const int m0 = blockIdx.y * BM;
    const int b  = m0 >> 11;

    float* hb_s  = (float*)(sm + OFF_HB);    // [128]
    float* wc_s  = (float*)(sm + OFF_WC);    // [128]
    float* v_s   = (float*)(sm + OFF_V);     // [128]
    float* cov_s = (float*)(sm + OFF_COV);   // [256]
    float* sc_s  = (float*)(sm + OFF_SC);    // [256]

    const uint32_t sbase = smem_u32(sm);
    const uint32_t mbF   = sbase + OFF_MBAR;
    const uint32_t mbE   = sbase + OFF_MBARE;

    if (tid == 0) {
        #pragma unroll
        for (int p = 0; p < NST; p++) {
            mbar_init(mbF + p * 8, 1);    // full: tx-based
            mbar_init(mbE + p * 8, 16);   // empty: one arrive per warp
        }
    }
    __syncthreads();
    fence_proxy_async_cta();

    const __half* Ablk = g_Xh  + (size_t)blockIdx.y * KSTAGES * A_BLK_H;
    const __half* Bblk = g_Wth + (size_t)blockIdx.x * KSTAGES * B_BLK_H;

    // prologue: issue stages 0..2 (buffer 3 issued at s=0 inside loop)
    if (tid == 0) {
        #pragma unroll
        for (int p = 0; p < 3; p++) {
            mbar_expect_tx(mbF + p * 8, STG);
            bulk_ld(sbase + p * STG,         Ablk + (size_t)p * A_BLK_H, STG_A, mbF + p * 8);
            bulk_ld(sbase + p * STG + STG_A, Bblk + (size_t)p * B_BLK_H, STG - STG_A, mbF + p * 8);
        }
    }

    if (tid < 128) {
        hb_s[tid] = g_hbias[b * UU + n0 + tid];
        wc_s[tid] = Wcw[n0 + tid];
        v_s[tid]  = Vw[n0 + tid];
    }
    if (tid >= 128 && tid < 384) {
        cov_s[tid - 128] = cov[m0 + tid - 128];
        sc_s[tid - 128] = 0.f;
    }
    __syncthreads();   // smem init visible to all warps; last CTA-wide barrier
                       // before the epilogue.

    // ldmatrix per-thread invariants
    const uint32_t slane = lane & 7;
    const uint32_t ahi   = lane >> 4;           // A chunk bit
    const uint32_t bbit  = (lane >> 3) & 1;     // B chunk bit
    uint32_t arow_off[4], brow_off[2];
    #pragma unroll
    for (int mi = 0; mi < 4; mi++)
        arow_off[mi] = (uint32_t)((wm * 64 + mi * 16 + (lane & 15)) << 7);
    #pragma unroll
    for (int njp = 0; njp < 2; njp++)
        brow_off[njp] = (uint32_t)(((wn * 32 + njp * 16 + slane + (ahi << 3)) << 7)
                                   + STG_A);

    float acc[4][4][4] = {};

    #define LOAD_FRAGS(ST_, KK_, AF_, BF_) do {                               \
        const uint32_t xa_ = ((((KK_) << 1) + ahi)  ^ slane) << 4;            \
        const uint32_t xb_ = ((((KK_) << 1) + bbit) ^ slane) << 4;            \
        _Pragma("unroll")                                                     \
        for (int mi_ = 0; mi_ < 4; mi_++)                                     \
            ldsm4(AF_[mi_], (ST_) + arow_off[mi_] + xa_);                     \
        _Pragma("unroll")                                                     \
        for (int nj_ = 0; nj_ < 2; nj_++)                                     \
            ldsm4(BF_[nj_], (ST_) + brow_off[nj_] + xb_);                     \
    } while (0)

    for (int s = 0; s < KSTAGES; s++) {
        // Producer: issue stage s+3 into buffer (s+3)%4 (= buffer of s-1).
        if (tid == 0 && s + 3 < KSTAGES) {
            const int p = (s + 3) % NST;
            if (s >= 1)   // buffer previously consumed at stage s-1
                mbar_wait(mbE + p * 8, (uint32_t)(((s - 1) >> 2) & 1));
            mbar_expect_tx(mbF + p * 8, STG);
            bulk_ld(sbase + p * STG,         Ablk + (size_t)(s + 3) * A_BLK_H, STG_A, mbF + p * 8);
            bulk_ld(sbase + p * STG + STG_A, Bblk + (size_t)(s + 3) * B_BLK_H, STG - STG_A, mbF + p * 8);
        }

        // Consumer: wait for stage s data.
        mbar_wait(mbF + (s % NST) * 8, (uint32_t)((s >> 2) & 1));

        const uint32_t st = sbase + (s % NST) * STG;

        uint32_t af[2][4][4], bf[2][2][4];
        LOAD_FRAGS(st, 0, af[0], bf[0]);

        #pragma unroll
        for (int kk = 0; kk < 4; kk++) {
            const int cur = kk & 1, nxt = cur ^ 1;
            if (kk < 3) LOAD_FRAGS(st, kk + 1, af[nxt], bf[nxt]);
            #pragma unroll
            for (int mi = 0; mi < 4; mi++) {
                #pragma unroll
                for (int njp = 0; njp < 2; njp++) {
                    mma_f16(acc[mi][2*njp    ], af[cur][mi], &bf[cur][njp][0]);
                    mma_f16(acc[mi][2*njp + 1], af[cur][mi], &bf[cur][njp][2]);
                }
            }
        }

        // This warp is done reading buffer s%4 (all LDSM completed: the final
        // HMMA above consumed them, and HMMA issue requires LDSM writeback).
        if (lane == 0) mbar_arrive(mbE + (s % NST) * 8);
    }

    // Epilogue: tanh + dot with V, reduce per token row.
    #pragma unroll
    for (int mi = 0; mi < 4; mi++) {
        const int mr = wm * 64 + mi * 16 + r;
        const float cv0 = cov_s[mr], cv1 = cov_s[mr + 8];
        float s0 = 0.f, s1 = 0.f;
        #pragma unroll
        for (int nj = 0; nj < 4; nj++) {
            #pragma unroll
            for (int e = 0; e < 2; e++) {
                const int u = wn * 32 + nj * 8 + 2 * c + e;
                const float hb = hb_s[u], wc = wc_s[u], vv = v_s[u];
                s0 += vv * fast_tanh(acc[mi][nj][e]     + hb + cv0 * wc);
                s1 += vv * fast_tanh(acc[mi][nj][e + 2] + hb + cv1 * wc);
            }
        }
        s0 += __shfl_xor_sync(0xffffffffu, s0, 1);
        s0 += __shfl_xor_sync(0xffffffffu, s0, 2);
        s1 += __shfl_xor_sync(0xffffffffu, s1, 1);
        s1 += __shfl_xor_sync(0xffffffffu, s1, 2);
        if (c == 0) {
            atomicAdd(&sc_s[mr],     s0);
            atomicAdd(&sc_s[mr + 8], s1);
        }
    }
    __syncthreads();
    if (tid < 256) atomicAdd(&g_score[m0 + tid], sc_s[tid]);
}

// ---------------------------------------------------------------------------
// Kernel C1: softmax over S per batch; write attn + coverage; zero ctx region.
// ---------------------------------------------------------------------------
__global__ void softmax_cov_kernel(const float* __restrict__ prev_cov,
                                   float* __restrict__ out) {
    __shared__ float red[256];
    const int b = blockIdx.x, tid = threadIdx.x;
    const int base = b * SS;

    float l[8];
    float mx = -1e30f;
    #pragma unroll
    for (int i = 0; i < 8; i++) {
        l[i] = g_score[base + i * 256 + tid];
        mx = fmaxf(mx, l[i]);
    }
    red[tid] = mx; __syncthreads();
    for (int o = 128; o > 0; o >>= 1) {
        if (tid < o) red[tid] = fmaxf(red[tid], red[tid + o]);
        __syncthreads();
    }
    const float gmax = red[0];
    __syncthreads();

    float s = 0.f;
    #pragma unroll
    for (int i = 0; i < 8; i++) { l[i] = expf(l[i] - gmax); s += l[i]; }
    red[tid] = s; __syncthreads();
    for (int o = 128; o > 0; o >>= 1) {
        if (tid < o) red[tid] += red[tid + o];
        __syncthreads();
    }
    const float inv = 1.f / red[0];

    #pragma unroll
    for (int i = 0; i < 8; i++) {
        const int idx = base + i * 256 + tid;
        const float w = l[i] * inv;
        out[ATTN_OFF + idx] = w;
        out[COV_OFF + idx]  = w + prev_cov[idx];
    }
    for (int i = tid; i < DD; i += 256) out[CTX_OFF + b * DD + i] = 0.f;
}

// ---------------------------------------------------------------------------
// Kernel C2: context[b,d] = sum_s attn[b,s] * X[b,s,d], blocked g_Xh.
// One thread per 16B chunk (8 d-values); 128 threads; grid (B=32, SSPLIT=16).
// ---------------------------------------------------------------------------
__global__ void context_kernel(float* __restrict__ out) {
    __shared__ float aw[128];
    const int tid = threadIdx.x;          // 0..127 = (kt,ch)
    const int b = blockIdx.x;
    const int sbeg = blockIdx.y * 128;

    aw[tid] = out[ATTN_OFF + b * SS + sbeg + tid];
    __syncthreads();

    const int kt = tid >> 3, ch = tid & 7;
    const int mbase = b * SS + sbeg;
    float acc[8] = {};

    #pragma unroll 4
    for (int s = 0; s < 128; s++) {
        const int m = mbase + s;
        const int mt = m >> 8, row = m & 255;
        const char* blk = (const char*)(g_Xh + ((size_t)mt * KSTAGES + kt) * A_BLK_H);
        const uint4 v = *(const uint4*)(blk + (row << 7) + ((ch ^ (row & 7)) << 4));
        const __half2* h = (const __half2*)&v;
        const float w = aw[s];
        #pragma unroll
        for (int j = 0; j < 4; j++) {
            const float2 f = __half22float2(h[j]);
            acc[2*j]   += w * f.x;
            acc[2*j+1] += w * f.y;
        }
    }
    const int d = kt * 64 + ch * 8;
    #pragma unroll
    for (int j = 0; j < 8; j++)
        atomicAdd(&out[CTX_OFF + b * DD + d + j], acc[j]);
}

// ---------------------------------------------------------------------------
extern "C" void kernel_launch(void* const* d_in, const int* in_sizes, int n_in,
                              void* d_out, int out_size) {
    int base = 3;
    if (n_in > 4 && in_sizes[3] != BS) base = 4;  // skip use_coverage scalar if present

    const float* dec      = (const float*)d_in[0];
    const float* enc      = (const float*)d_in[1];
    const float* prev_cov = (const float*)d_in[base + 0];
    const float* Ws_w     = (const float*)d_in[base + 1];
    const float* Ws_b     = (const float*)d_in[base + 2];
    const float* Wh_w     = (const float*)d_in[base + 3];
    const float* Wh_b     = (const float*)d_in[base + 4];
    const float* Wc_w     = (const float*)d_in[base + 5];
    const float* Wc_b     = (const float*)d_in[base + 6];
    const float* V_w      = (const float*)d_in[base + 7];
    // V_b unused: softmax is shift-invariant.

    float* out = (float*)d_out;

    cudaFuncSetAttribute(score_gemm_fp16,
                         cudaFuncAttributeMaxDynamicSharedMemorySize, SMEM_NEED);

    convert_x_kernel<<<16384, 512>>>(enc);
    transpose_w_kernel<<<dim3(UU / 32, DD / 32), dim3(32, 8)>>>(Ws_w);
    hbias_kernel<<<dim3(UU / 256, BB), 256>>>(dec, Wh_w, Wh_b, Ws_b, Wc_b);
    score_gemm_fp16<<<dim3(UU / BN, BS / BM), 512, SMEM_NEED>>>(Wc_w, V_w, prev_cov);
    softmax_cov_kernel<<<BB, 256>>>(prev_cov, out);
    context_kernel<<<dim3(BB, 16), 128>>>(out);
    (void)out_size;
}

// round 10
// speedup vs baseline: 2.6288x; 1.1081x over previous
#include <cuda_runtime.h>
#include <cuda_fp16.h>
#include <cstdint>

// Problem constants
#define BB 32
#define SS 2048
#define DD 1024
#define UU 1024
#define BS (BB*SS)            // 65536 tokens

// Output layout: context [B,D] | attn [B,S] | coverage [B,S]
#define CTX_OFF 0
#define ATTN_OFF (BB*DD)
#define COV_OFF  (BB*DD + BB*SS)

// GEMM tiling
#define BM 256
#define BN 128
#define BKH 64                         // K-chunk in halves (128B rows)
#define KSTAGES 16                     // DD / BKH
#define NTILES 2048                    // (BS/BM) * (UU/BN)
#define A_BLK_H 16384                  // halves per A tile block (256*64) = 32KB
#define B_BLK_H 8192                   // halves per B tile block (128*64) = 16KB

// Device scratch (allocation-free rule: __device__ globals)
__device__ float  g_hbias[BB*UU];          // dec@Wh + Wh_b + Ws_b + Wc_b
__device__ float  g_score[BS];             // pre-softmax scores
__device__ __half g_Xh[(size_t)BS*DD];     // enc_output fp16, tile-blocked+swizzled
__device__ __half g_Wth[UU*DD];            // Ws_w^T fp16, tile-blocked+swizzled

// ---------------------------------------------------------------------------
// helpers
// ---------------------------------------------------------------------------
__device__ __forceinline__ uint32_t smem_u32(const void* p) {
    uint32_t a;
    asm("{ .reg .u64 t; cvta.to.shared.u64 t, %1; cvt.u32.u64 %0, t; }"
        : "=r"(a) : "l"(p));
    return a;
}

__device__ __forceinline__ void mbar_init(uint32_t addr, uint32_t cnt) {
    asm volatile("mbarrier.init.shared.b64 [%0], %1;" :: "r"(addr), "r"(cnt) : "memory");
}

__device__ __forceinline__ void mbar_expect_tx(uint32_t addr, uint32_t bytes) {
    asm volatile("mbarrier.arrive.expect_tx.shared.b64 _, [%0], %1;"
                 :: "r"(addr), "r"(bytes) : "memory");
}

__device__ __forceinline__ void mbar_arrive(uint32_t addr) {
    asm volatile("mbarrier.arrive.shared.b64 _, [%0];" :: "r"(addr) : "memory");
}

__device__ __forceinline__ void mbar_wait(uint32_t addr, uint32_t parity) {
    asm volatile(
        "{\n\t.reg .pred P;\n"
        "WAIT_%=: \n\t"
        "mbarrier.try_wait.parity.acquire.cta.shared::cta.b64 P, [%0], %1, 0x989680;\n\t"
        "@P bra DONE_%=;\n\t"
        "bra WAIT_%=;\n"
        "DONE_%=: \n\t}"
        :: "r"(addr), "r"(parity) : "memory");
}

__device__ __forceinline__ void bulk_ld(uint32_t sdst, const void* gsrc,
                                        uint32_t bytes, uint32_t mbar) {
    asm volatile(
        "cp.async.bulk.shared::cta.global.mbarrier::complete_tx::bytes "
        "[%0], [%1], %2, [%3];"
        :: "r"(sdst), "l"(gsrc), "r"(bytes), "r"(mbar) : "memory");
}

__device__ __forceinline__ void fence_proxy_async_cta() {
    asm volatile("fence.proxy.async.shared::cta;" ::: "memory");
}

__device__ __forceinline__ void ldsm4(uint32_t* r, uint32_t addr) {
    asm volatile("ldmatrix.sync.aligned.m8n8.x4.shared.b16 {%0,%1,%2,%3}, [%4];"
                 : "=r"(r[0]), "=r"(r[1]), "=r"(r[2]), "=r"(r[3]) : "r"(addr));
}

__device__ __forceinline__ void mma_f16(float* d, const uint32_t* a, const uint32_t* b) {
    asm volatile(
        "mma.sync.aligned.m16n8k16.row.col.f32.f16.f16.f32 "
        "{%0,%1,%2,%3}, {%4,%5,%6,%7}, {%8,%9}, {%0,%1,%2,%3};\n"
        : "+f"(d[0]), "+f"(d[1]), "+f"(d[2]), "+f"(d[3])
        : "r"(a[0]), "r"(a[1]), "r"(a[2]), "r"(a[3]),
          "r"(b[0]), "r"(b[1]));
}

__device__ __forceinline__ float fast_tanh(float x) {
    float t;
    asm("tanh.approx.f32 %0, %1;" : "=f"(t) : "f"(x));
    return t;
}

// ---------------------------------------------------------------------------
// Mega prep kernel: blocks [0,1024) transpose Ws, [1024,1088) hbias+score0,
// [1088,17472) convert X. All 512 threads.
// ---------------------------------------------------------------------------
__global__ void __launch_bounds__(512)
prep_kernel(const float* __restrict__ X,
            const float* __restrict__ W,
            const float* __restrict__ dec,
            const float* __restrict__ Whw,
            const float* __restrict__ Whb,
            const float* __restrict__ Wsb,
            const float* __restrict__ Wcb) {
    __shared__ float sbuf[1184];
    const int bid = blockIdx.x;
    const int tid = threadIdx.x;

    if (bid < 1024) {
        // ----- transpose+convert Ws_w [D,U] -> g_Wth tile-blocked swizzled
        float (*t)[33] = (float(*)[33])sbuf;
        const int tx = tid & 31, ty = tid >> 5;          // ty 0..15
        const int bx = (bid & 31) * 32;                   // u base
        const int by = (bid >> 5) * 32;                   // d base
        #pragma unroll
        for (int j = 0; j < 2; j++)
            t[ty + j * 16][tx] = W[(size_t)(by + ty + j * 16) * UU + bx + tx];
        __syncthreads();
        #pragma unroll
        for (int j = 0; j < 2; j++) {
            const int u = bx + ty + j * 16;
            const int d = by + tx;
            const int nt = u >> 7, rowB = u & 127;
            const int kt = d >> 6, ch = (d & 63) >> 3, pos = d & 7;
            char* blk = (char*)(g_Wth + ((size_t)nt * KSTAGES + kt) * B_BLK_H);
            *(__half*)(blk + (rowB << 7) + ((ch ^ (rowB & 7)) << 4) + pos * 2) =
                __float2half(t[tx][ty + j * 16]);
        }
    } else if (bid < 1088) {
        // ----- hbias + zero g_score
        float* dh = sbuf;
        const int lb = bid - 1024;
        const int b = lb >> 1;
        const int u = (lb & 1) * 512 + tid;
        dh[tid] = dec[b * DD + tid];
        dh[tid + 512] = dec[b * DD + tid + 512];
        __syncthreads();

        float a0 = 0.f, a1 = 0.f, a2 = 0.f, a3 = 0.f;
        #pragma unroll 4
        for (int d = 0; d < DD; d += 4) {
            a0 += dh[d+0] * Whw[(size_t)(d+0)*UU + u];
            a1 += dh[d+1] * Whw[(size_t)(d+1)*UU + u];
            a2 += dh[d+2] * Whw[(size_t)(d+2)*UU + u];
            a3 += dh[d+3] * Whw[(size_t)(d+3)*UU + u];
        }
        g_hbias[b*UU + u] = (a0 + a1) + (a2 + a3) + Whb[u] + Wsb[u] + Wcb[u];

        const int gid = lb * 512 + tid;
        g_score[gid] = 0.f;
        g_score[gid + 32768] = 0.f;
    } else {
        // ----- convert enc fp32 -> fp16 tile-blocked swizzled
        const size_t i = (size_t)(bid - 1088) * 512 + tid;
        const int m  = (int)(i >> 7);
        const int cg = (int)(i & 127);
        const int kt = cg >> 3;
        const int ch = cg & 7;
        const int mt = m >> 8;
        const int row = m & 255;

        const float4* src = (const float4*)(X + (size_t)m * DD + kt * 64 + ch * 8);
        const float4 f0 = src[0];
        const float4 f1 = src[1];
        __half2 h0 = __float22half2_rn(make_float2(f0.x, f0.y));
        __half2 h1 = __float22half2_rn(make_float2(f0.z, f0.w));
        __half2 h2 = __float22half2_rn(make_float2(f1.x, f1.y));
        __half2 h3 = __float22half2_rn(make_float2(f1.z, f1.w));
        uint4 o;
        o.x = *(uint32_t*)&h0; o.y = *(uint32_t*)&h1;
        o.z = *(uint32_t*)&h2; o.w = *(uint32_t*)&h3;

        char* blk = (char*)(g_Xh + ((size_t)mt * KSTAGES + kt) * A_BLK_H);
        *(uint4*)(blk + (row << 7) + ((ch ^ (row & 7)) << 4)) = o;
    }
}

// ---------------------------------------------------------------------------
// Kernel B: PERSISTENT fp16 mma.sync fused score GEMM.
// grid = #SMs; each CTA loops tiles (tile = bid + k*gridDim).
// Pipeline (4-deep bulk-copy + full/empty mbarriers) runs continuously across
// tile boundaries; per-tile operand arrays parity-double-buffered; score
// reduction via direct global atomics (no per-tile __syncthreads).
// ---------------------------------------------------------------------------
#define NST 4
#define STG 49152                      // 32KB A + 16KB B
#define STG_A 32768
#define OFF_SMALL (NST*STG)            // 196608; 2 x 640 floats
#define OFF_MBAR  (OFF_SMALL + 5120)   // 4 full mbarriers
#define OFF_MBARE (OFF_MBAR + 32)      // 4 empty mbarriers
#define SMEM_NEED (OFF_MBARE + 32)     // 201792

__global__ void __launch_bounds__(512, 1)
score_gemm_fp16(const float* __restrict__ Wcw,
                const float* __restrict__ Vw,
                const float* __restrict__ cov) {
    extern __shared__ char sm[];
    const int tid  = threadIdx.x;
    const int lane = tid & 31;
    const int wid  = tid >> 5;
    const int wm   = wid >> 2;        // 0..3
    const int wn   = wid & 3;         // 0..3
    const int r    = lane >> 2;       // 0..7
    const int c    = lane & 3;        // 0..3

    const uint32_t sbase = smem_u32(sm);
    const uint32_t mbF   = sbase + OFF_MBAR;
    const uint32_t mbE   = sbase + OFF_MBARE;
    const int grid = gridDim.x;
    const int ntiles = (NTILES - blockIdx.x + grid - 1) / grid;
    const int total_gs = ntiles * KSTAGES;

    if (tid == 0) {
        #pragma unroll
        for (int p = 0; p < NST; p++) {
            mbar_init(mbF + p * 8, 1);    // full: tx-based
            mbar_init(mbE + p * 8, 16);   // empty: one arrive per warp
        }
    }

    // per-tile small operands, parity buffers (640 floats each)
    float* small0 = (float*)(sm + OFF_SMALL);

    // load tile 0 arrays into parity 0
    {
        const int t0 = blockIdx.x;
        const int m0 = (t0 >> 3) * BM, n0 = (t0 & 7) * BN, b = m0 >> 11;
        if (tid < 128) {
            small0[tid]       = g_hbias[b * UU + n0 + tid];
            small0[128 + tid] = Wcw[n0 + tid];
            small0[256 + tid] = Vw[n0 + tid];
        } else if (tid < 384) {
            small0[384 + tid - 128] = cov[m0 + tid - 128];
        }
    }
    __syncthreads();
    fence_proxy_async_cta();

    // prologue: issue stages 0..2 of first tile
    if (tid == 0) {
        const int t0 = blockIdx.x;
        const __half* Ab = g_Xh  + (size_t)(t0 >> 3) * KSTAGES * A_BLK_H;
        const __half* Bb = g_Wth + (size_t)(t0 & 7)  * KSTAGES * B_BLK_H;
        #pragma unroll
        for (int p = 0; p < 3; p++) {
            mbar_expect_tx(mbF + p * 8, STG);
            bulk_ld(sbase + p * STG,         Ab + (size_t)p * A_BLK_H, STG_A, mbF + p * 8);
            bulk_ld(sbase + p * STG + STG_A, Bb + (size_t)p * B_BLK_H, STG - STG_A, mbF + p * 8);
        }
    }

    // ldmatrix per-thread invariants
    const uint32_t slane = lane & 7;
    const uint32_t ahi   = lane >> 4;
    const uint32_t bbit  = (lane >> 3) & 1;
    uint32_t arow_off[4], brow_off[2];
    #pragma unroll
    for (int mi = 0; mi < 4; mi++)
        arow_off[mi] = (uint32_t)((wm * 64 + mi * 16 + (lane & 15)) << 7);
    #pragma unroll
    for (int njp = 0; njp < 2; njp++)
        brow_off[njp] = (uint32_t)(((wn * 32 + njp * 16 + slane + (ahi << 3)) << 7)
                                   + STG_A);

    #define LOAD_FRAGS(ST_, KK_, AF_, BF_) do {                               \
        const uint32_t xa_ = ((((KK_) << 1) + ahi)  ^ slane) << 4;            \
        const uint32_t xb_ = ((((KK_) << 1) + bbit) ^ slane) << 4;            \
        _Pragma("unroll")                                                     \
        for (int mi_ = 0; mi_ < 4; mi_++)                                     \
            ldsm4(AF_[mi_], (ST_) + arow_off[mi_] + xa_);                     \
        _Pragma("unroll")                                                     \
        for (int nj_ = 0; nj_ < 2; nj_++)                                     \
            ldsm4(BF_[nj_], (ST_) + brow_off[nj_] + xb_);                     \
    } while (0)

    int gs = 0;
    for (int tt = 0; tt < ntiles; tt++) {
        const int tile = blockIdx.x + tt * grid;
        const int m0 = (tile >> 3) * BM;
        const int n0 = (tile & 7) * BN;
        const int b  = m0 >> 11;
        float* sa = small0 + (tt & 1) * 640;

        // load THIS tile's arrays (tt==0 already loaded before the sync).
        // Safe without barrier: warp skew <= NST-1 stages; parity alternates.
        if (tt > 0) {
            if (tid < 128) {
                sa[tid]       = g_hbias[b * UU + n0 + tid];
                sa[128 + tid] = Wcw[n0 + tid];
                sa[256 + tid] = Vw[n0 + tid];
            } else if (tid < 384) {
                sa[384 + tid - 128] = cov[m0 + tid - 128];
            }
        }

        float acc[4][4][4] = {};

        for (int s = 0; s < KSTAGES; s++, gs++) {
            // Producer: issue global stage gs+3.
            if (tid == 0) {
                const int fgs = gs + 3;
                if (fgs < total_gs) {
                    const int p = fgs & 3;
                    if (gs >= 1)
                        mbar_wait(mbE + p * 8, (uint32_t)(((gs - 1) >> 2) & 1));
                    const int ft = blockIdx.x + (fgs >> 4) * grid;
                    const __half* Ab = g_Xh  + ((size_t)(ft >> 3) * KSTAGES + (fgs & 15)) * A_BLK_H;
                    const __half* Bb = g_Wth + ((size_t)(ft & 7)  * KSTAGES + (fgs & 15)) * B_BLK_H;
                    mbar_expect_tx(mbF + p * 8, STG);
                    bulk_ld(sbase + p * STG,         Ab, STG_A, mbF + p * 8);
                    bulk_ld(sbase + p * STG + STG_A, Bb, STG - STG_A, mbF + p * 8);
                }
            }

            mbar_wait(mbF + (gs & 3) * 8, (uint32_t)((gs >> 2) & 1));

            const uint32_t st = sbase + (gs & 3) * STG;

            uint32_t af[2][4][4], bf[2][2][4];
            LOAD_FRAGS(st, 0, af[0], bf[0]);

            #pragma unroll
            for (int kk = 0; kk < 4; kk++) {
                const int cur = kk & 1, nxt = cur ^ 1;
                if (kk < 3) LOAD_FRAGS(st, kk + 1, af[nxt], bf[nxt]);
                #pragma unroll
                for (int mi = 0; mi < 4; mi++) {
                    #pragma unroll
                    for (int njp = 0; njp < 2; njp++) {
                        mma_f16(acc[mi][2*njp    ], af[cur][mi], &bf[cur][njp][0]);
                        mma_f16(acc[mi][2*njp + 1], af[cur][mi], &bf[cur][njp][2]);
                    }
                }
            }

            if (lane == 0) mbar_arrive(mbE + (gs & 3) * 8);
        }

        // Epilogue: tanh + dot with V; direct global atomics (overlaps with
        // the TMA fills of the next tile already in flight).
        const float* hb_s  = sa;
        const float* wc_s  = sa + 128;
        const float* v_s   = sa + 256;
        const float* cov_s = sa + 384;
        #pragma unroll
        for (int mi = 0; mi < 4; mi++) {
            const int mr = wm * 64 + mi * 16 + r;
            const float cv0 = cov_s[mr], cv1 = cov_s[mr + 8];
            float s0 = 0.f, s1 = 0.f;
            #pragma unroll
            for (int nj = 0; nj < 4; nj++) {
                #pragma unroll
                for (int e = 0; e < 2; e++) {
                    const int u = wn * 32 + nj * 8 + 2 * c + e;
                    const float hb = hb_s[u], wc = wc_s[u], vv = v_s[u];
                    s0 += vv * fast_tanh(acc[mi][nj][e]     + hb + cv0 * wc);
                    s1 += vv * fast_tanh(acc[mi][nj][e + 2] + hb + cv1 * wc);
                }
            }
            s0 += __shfl_xor_sync(0xffffffffu, s0, 1);
            s0 += __shfl_xor_sync(0xffffffffu, s0, 2);
            s1 += __shfl_xor_sync(0xffffffffu, s1, 1);
            s1 += __shfl_xor_sync(0xffffffffu, s1, 2);
            if (c == 0) {
                atomicAdd(&g_score[m0 + mr],     s0);
                atomicAdd(&g_score[m0 + mr + 8], s1);
            }
        }
    }
}

// ---------------------------------------------------------------------------
// Kernel C1: softmax over S per batch; write attn + coverage; zero ctx region.
// ---------------------------------------------------------------------------
__global__ void softmax_cov_kernel(const float* __restrict__ prev_cov,
                                   float* __restrict__ out) {
    __shared__ float red[256];
    const int b = blockIdx.x, tid = threadIdx.x;
    const int base = b * SS;

    float l[8];
    float mx = -1e30f;
    #pragma unroll
    for (int i = 0; i < 8; i++) {
        l[i] = g_score[base + i * 256 + tid];
        mx = fmaxf(mx, l[i]);
    }
    red[tid] = mx; __syncthreads();
    for (int o = 128; o > 0; o >>= 1) {
        if (tid < o) red[tid] = fmaxf(red[tid], red[tid + o]);
        __syncthreads();
    }
    const float gmax = red[0];
    __syncthreads();

    float s = 0.f;
    #pragma unroll
    for (int i = 0; i < 8; i++) { l[i] = expf(l[i] - gmax); s += l[i]; }
    red[tid] = s; __syncthreads();
    for (int o = 128; o > 0; o >>= 1) {
        if (tid < o) red[tid] += red[tid + o];
        __syncthreads();
    }
    const float inv = 1.f / red[0];

    #pragma unroll
    for (int i = 0; i < 8; i++) {
        const int idx = base + i * 256 + tid;
        const float w = l[i] * inv;
        out[ATTN_OFF + idx] = w;
        out[COV_OFF + idx]  = w + prev_cov[idx];
    }
    for (int i = tid; i < DD; i += 256) out[CTX_OFF + b * DD + i] = 0.f;
}

// ---------------------------------------------------------------------------
// Kernel C2: context[b,d] = sum_s attn[b,s] * X[b,s,d], blocked g_Xh.
// ---------------------------------------------------------------------------
__global__ void context_kernel(float* __restrict__ out) {
    __shared__ float aw[128];
    const int tid = threadIdx.x;          // 0..127 = (kt,ch)
    const int b = blockIdx.x;
    const int sbeg = blockIdx.y * 128;

    aw[tid] = out[ATTN_OFF + b * SS + sbeg + tid];
    __syncthreads();

    const int kt = tid >> 3, ch = tid & 7;
    const int mbase = b * SS + sbeg;
    float acc[8] = {};

    #pragma unroll 4
    for (int s = 0; s < 128; s++) {
        const int m = mbase + s;
        const int mt = m >> 8, row = m & 255;
        const char* blk = (const char*)(g_Xh + ((size_t)mt * KSTAGES + kt) * A_BLK_H);
        const uint4 v = *(const uint4*)(blk + (row << 7) + ((ch ^ (row & 7)) << 4));
        const __half2* h = (const __half2*)&v;
        const float w = aw[s];
        #pragma unroll
        for (int j = 0; j < 4; j++) {
            const float2 f = __half22float2(h[j]);
            acc[2*j]   += w * f.x;
            acc[2*j+1] += w * f.y;
        }
    }
    const int d = kt * 64 + ch * 8;
    #pragma unroll
    for (int j = 0; j < 8; j++)
        atomicAdd(&out[CTX_OFF + b * DD + d + j], acc[j]);
}

// ---------------------------------------------------------------------------
extern "C" void kernel_launch(void* const* d_in, const int* in_sizes, int n_in,
                              void* d_out, int out_size) {
    int base = 3;
    if (n_in > 4 && in_sizes[3] != BS) base = 4;  // skip use_coverage scalar if present

    const float* dec      = (const float*)d_in[0];
    const float* enc      = (const float*)d_in[1];
    const float* prev_cov = (const float*)d_in[base + 0];
    const float* Ws_w     = (const float*)d_in[base + 1];
    const float* Ws_b     = (const float*)d_in[base + 2];
    const float* Wh_w     = (const float*)d_in[base + 3];
    const float* Wh_b     = (const float*)d_in[base + 4];
    const float* Wc_w     = (const float*)d_in[base + 5];
    const float* Wc_b     = (const float*)d_in[base + 6];
    const float* V_w      = (const float*)d_in[base + 7];
    // V_b unused: softmax is shift-invariant.

    float* out = (float*)d_out;

    int nsm = 148;
    cudaDeviceGetAttribute(&nsm, cudaDevAttrMultiProcessorCount, 0);

    cudaFuncSetAttribute(score_gemm_fp16,
                         cudaFuncAttributeMaxDynamicSharedMemorySize, SMEM_NEED);

    prep_kernel<<<17472, 512>>>(enc, Ws_w, dec, Wh_w, Wh_b, Ws_b, Wc_b);
    score_gemm_fp16<<<nsm, 512, SMEM_NEED>>>(Wc_w, V_w, prev_cov);
    softmax_cov_kernel<<<BB, 256>>>(prev_cov, out);
    context_kernel<<<dim3(BB, 16), 128>>>(out);
    (void)out_size;
}